// round 1
// baseline (speedup 1.0000x reference)
#include <cuda_runtime.h>

typedef unsigned long long ull;

#define NIMG 8
#define CH 64
#define HW 16384           // 128*128
#define IMGSZ (CH*HW)      // 1048576 floats per image

// Scratch (device globals; no runtime allocation allowed)
__device__ float g_uf[NIMG*IMGSZ];
__device__ float g_vf[NIMG*IMGSZ];
__device__ float g_ou[NIMG*IMGSZ];
__device__ float g_ov[NIMG*IMGSZ];
__device__ float g_wT[128*9*64];   // [ci_global][k][co]

// ---- packed f32x2 helpers (B300: FFMA2 is PTX-only, 2x FP32 throughput) ----
__device__ __forceinline__ ull fma2(ull a, ull b, ull c){
  ull d; asm("fma.rn.f32x2 %0, %1, %2, %3;" : "=l"(d) : "l"(a), "l"(b), "l"(c)); return d;
}
__device__ __forceinline__ ull dup2(float x){
  ull r; asm("mov.b64 %0, {%1, %1};" : "=l"(r) : "f"(x)); return r;
}
__device__ __forceinline__ void unpk2(ull v, float& lo, float& hi){
  asm("mov.b64 {%0, %1}, %2;" : "=f"(lo), "=f"(hi) : "l"(v));
}

// ---------------------------------------------------------------------------
// K0: transpose conv weights (Co,128,3,3) -> g_wT[ci][k][co]
// ---------------------------------------------------------------------------
__global__ void k_transpose_w(const float* __restrict__ conv_w){
  int idx = blockIdx.x*256 + threadIdx.x;
  if (idx >= 128*9*64) return;
  int co = idx & 63;
  int k  = (idx >> 6) % 9;
  int ci = idx / 576;
  g_wT[idx] = conv_w[(co*128 + ci)*9 + k];
}

// ---------------------------------------------------------------------------
// K1: 1x1 conv + BN + ReLU.  block: 64 co x 256 pixels of one image.
// thread: 16 co x 4 pixels, co-paired f32x2 accumulators.
// ---------------------------------------------------------------------------
__global__ __launch_bounds__(256) void k_pointwise(
    const float* __restrict__ x, const float* __restrict__ w,
    const float* __restrict__ gamma, const float* __restrict__ beta,
    const float* __restrict__ mean, const float* __restrict__ var,
    int sel)
{
  __shared__ float sw[64*64];   // [ci][co]
  float* out = sel ? g_vf : g_uf;
  int tid = threadIdx.x;
  for (int i = tid; i < 4096; i += 256){
    int ci = i >> 6, co = i & 63;
    sw[i] = w[co*64 + ci];
  }
  __syncthreads();

  int img  = blockIdx.y;
  int lane = tid & 63;
  int cg   = tid >> 6;          // 0..3
  int co0  = cg * 16;
  int pix  = blockIdx.x*256 + lane*4;
  const float* xi = x + (size_t)img*IMGSZ;

  ull acc[8][4];
  #pragma unroll
  for (int p=0;p<8;p++)
    #pragma unroll
    for (int j=0;j<4;j++) acc[p][j]=0ull;

  #pragma unroll 4
  for (int ci=0; ci<64; ++ci){
    float4 xv = *(const float4*)(xi + ci*HW + pix);
    ull x0=dup2(xv.x), x1=dup2(xv.y), x2=dup2(xv.z), x3=dup2(xv.w);
    const ulonglong2* wp = (const ulonglong2*)(sw + ci*64 + co0);
    ulonglong2 w0=wp[0], w1=wp[1], w2=wp[2], w3=wp[3];
    ull wv[8] = {w0.x,w0.y,w1.x,w1.y,w2.x,w2.y,w3.x,w3.y};
    #pragma unroll
    for (int p=0;p<8;p++){
      acc[p][0]=fma2(wv[p],x0,acc[p][0]);
      acc[p][1]=fma2(wv[p],x1,acc[p][1]);
      acc[p][2]=fma2(wv[p],x2,acc[p][2]);
      acc[p][3]=fma2(wv[p],x3,acc[p][3]);
    }
  }

  #pragma unroll
  for (int p=0;p<8;p++){
    int coa = co0 + 2*p, cob = coa + 1;
    float la = gamma[coa]*rsqrtf(var[coa]+1e-5f);
    float sa = beta[coa] - mean[coa]*la;
    float lb = gamma[cob]*rsqrtf(var[cob]+1e-5f);
    float sb = beta[cob] - mean[cob]*lb;
    float4 oa, ob;
    float lo, hi;
    unpk2(acc[p][0], lo, hi); oa.x=fmaxf(fmaf(lo,la,sa),0.f); ob.x=fmaxf(fmaf(hi,lb,sb),0.f);
    unpk2(acc[p][1], lo, hi); oa.y=fmaxf(fmaf(lo,la,sa),0.f); ob.y=fmaxf(fmaf(hi,lb,sb),0.f);
    unpk2(acc[p][2], lo, hi); oa.z=fmaxf(fmaf(lo,la,sa),0.f); ob.z=fmaxf(fmaf(hi,lb,sb),0.f);
    unpk2(acc[p][3], lo, hi); oa.w=fmaxf(fmaf(lo,la,sa),0.f); ob.w=fmaxf(fmaf(hi,lb,sb),0.f);
    *(float4*)(out + (size_t)(img*64+coa)*HW + pix) = oa;
    *(float4*)(out + (size_t)(img*64+cob)*HW + pix) = ob;
  }
}

// ---------------------------------------------------------------------------
// K2: 3x3 conv, pad 1, Cin=64, Cout=64, per image.
// block: 64 co x (32w x 8h); thread: 8 co x 8 rows; cin chunked by 8.
// Weights broadcast from smem as contiguous co-pairs (no packing MOVs).
// ---------------------------------------------------------------------------
__global__ __launch_bounds__(256) void k_conv3x3(int sel)
{
  __shared__ float sin_t[8*10*34];   // [ci][row 0..9][col 0..33]  (10.6 KB)
  __shared__ float swt[8*9*64];      // [ci][k][co]                (18 KB)
  const float* in = sel ? g_vf : g_uf;
  float* out      = sel ? g_ov : g_ou;
  int ci_base = sel * 64;

  int tid  = threadIdx.x;
  int img  = blockIdx.z;
  int h0   = blockIdx.y * 8;
  int w0   = blockIdx.x * 32;
  int cg   = tid >> 5;              // 0..7 -> co = cg*8
  int lane = tid & 31;              // w offset
  const float* ib = in + (size_t)img*IMGSZ;

  ull acc[4][8];                    // [co-pair][row]
  #pragma unroll
  for (int p=0;p<4;p++)
    #pragma unroll
    for (int r=0;r<8;r++) acc[p][r]=0ull;

  for (int cc = 0; cc < 64; cc += 8){
    // stage input tile (with zero padding at image borders)
    for (int i = tid; i < 2720; i += 256){
      int ci  = i / 340;
      int rem = i - ci*340;
      int r   = rem / 34;
      int c   = rem - r*34;
      int gh  = h0 - 1 + r;
      int gw  = w0 - 1 + c;
      float v = 0.f;
      if ((unsigned)gh < 128u && (unsigned)gw < 128u)
        v = ib[((cc+ci)*128 + gh)*128 + gw];
      sin_t[i] = v;
    }
    // stage weights (contiguous copy thanks to g_wT layout)
    const float* wsrc = g_wT + (ci_base + cc)*576;
    for (int i = tid; i < 4608; i += 256) swt[i] = wsrc[i];
    __syncthreads();

    for (int ci = 0; ci < 8; ++ci){
      #pragma unroll
      for (int ky = 0; ky < 3; ++ky){
        #pragma unroll
        for (int kx = 0; kx < 3; ++kx){
          const ulonglong2* wp =
            (const ulonglong2*)(swt + ((ci*9 + ky*3 + kx)<<6) + (cg<<3));
          ulonglong2 wA = wp[0];
          ulonglong2 wB = wp[1];
          const float* ip = sin_t + ci*340 + ky*34 + lane + kx;
          #pragma unroll
          for (int r = 0; r < 8; ++r){
            ull xx = dup2(ip[r*34]);
            acc[0][r] = fma2(wA.x, xx, acc[0][r]);
            acc[1][r] = fma2(wA.y, xx, acc[1][r]);
            acc[2][r] = fma2(wB.x, xx, acc[2][r]);
            acc[3][r] = fma2(wB.y, xx, acc[3][r]);
          }
        }
      }
    }
    __syncthreads();
  }

  float* ob = out + (size_t)img*IMGSZ;
  #pragma unroll
  for (int p=0;p<4;p++){
    int coa = cg*8 + 2*p;
    #pragma unroll
    for (int r=0;r<8;r++){
      float lo, hi; unpk2(acc[p][r], lo, hi);
      int off = ((h0 + r)<<7) + w0 + lane;
      ob[(coa<<14) + off]       = lo;
      ob[((coa+1)<<14) + off]   = hi;
    }
  }
}

// ---------------------------------------------------------------------------
// K3: out[b,sx,sy,co,h,w] = ou[b*4+sx,co,h,w] + ov[b*4+sy,co,h,w] + bias[co]
// ---------------------------------------------------------------------------
__global__ void k_bcast_add(const float* __restrict__ bias, float* __restrict__ out){
  unsigned i = (blockIdx.x*256u + threadIdx.x)*4u;
  unsigned pix = i & 16383u;
  unsigned t = i >> 14;              // ((b*4+sx)*4+sy)*64+co
  unsigned co = t & 63u;
  unsigned s  = t >> 6;              // (b*4+sx)*4+sy
  unsigned sy = s & 3u;
  unsigned uimg = s >> 2;            // b*4+sx
  unsigned b  = uimg >> 2;
  unsigned vimg = b*4u + sy;
  float4 a = *(const float4*)(g_ou + (((size_t)(uimg*64u+co))<<14) + pix);
  float4 c = *(const float4*)(g_ov + (((size_t)(vimg*64u+co))<<14) + pix);
  float bi = __ldg(bias + co);
  float4 o;
  o.x = a.x + c.x + bi;
  o.y = a.y + c.y + bi;
  o.z = a.z + c.z + bi;
  o.w = a.w + c.w + bi;
  *(float4*)(out + i) = o;
}

// ---------------------------------------------------------------------------
extern "C" void kernel_launch(void* const* d_in, const int* in_sizes, int n_in,
                              void* d_out, int out_size)
{
  const float* u        = (const float*)d_in[0];
  const float* v        = (const float*)d_in[1];
  const float* pu_w     = (const float*)d_in[2];
  const float* pu_gamma = (const float*)d_in[3];
  const float* pu_beta  = (const float*)d_in[4];
  const float* pu_mean  = (const float*)d_in[5];
  const float* pu_var   = (const float*)d_in[6];
  const float* pv_w     = (const float*)d_in[7];
  const float* pv_gamma = (const float*)d_in[8];
  const float* pv_beta  = (const float*)d_in[9];
  const float* pv_mean  = (const float*)d_in[10];
  const float* pv_var   = (const float*)d_in[11];
  const float* conv_w   = (const float*)d_in[12];
  const float* conv_b   = (const float*)d_in[13];
  float* out = (float*)d_out;

  k_transpose_w<<<288, 256>>>(conv_w);

  dim3 pwg(64, 8);
  k_pointwise<<<pwg, 256>>>(u, pu_w, pu_gamma, pu_beta, pu_mean, pu_var, 0);
  k_pointwise<<<pwg, 256>>>(v, pv_w, pv_gamma, pv_beta, pv_mean, pv_var, 1);

  dim3 cgrid(4, 16, 8);
  k_conv3x3<<<cgrid, 256>>>(0);
  k_conv3x3<<<cgrid, 256>>>(1);

  k_bcast_add<<<32768, 256>>>(conv_b, out);
}

// round 3
// speedup vs baseline: 1.6649x; 1.6649x over previous
#include <cuda_runtime.h>
#include <cstdint>

typedef unsigned long long ull;

#define NIMG 8
#define HW 16384           // 128*128
#define IMGSZ (64*HW)      // 1048576 floats per image

// Scratch (device globals; no runtime allocation allowed)
__device__ float g_uf[NIMG*IMGSZ];
__device__ float g_vf[NIMG*IMGSZ];
__device__ float g_ou[NIMG*IMGSZ];
__device__ float g_ov[NIMG*IMGSZ];
// TF32-rounded transposed weights: [branch][ci(64)][tap(9)][co(64)]
__device__ uint32_t g_wT[2*64*9*64];

// ---- packed f32x2 helpers (pointwise kernel) ----
__device__ __forceinline__ ull fma2(ull a, ull b, ull c){
  ull d; asm("fma.rn.f32x2 %0, %1, %2, %3;" : "=l"(d) : "l"(a), "l"(b), "l"(c)); return d;
}
__device__ __forceinline__ ull dup2(float x){
  ull r; asm("mov.b64 %0, {%1, %1};" : "=l"(r) : "f"(x)); return r;
}
__device__ __forceinline__ void unpk2(ull v, float& lo, float& hi){
  asm("mov.b64 {%0, %1}, %2;" : "=f"(lo), "=f"(hi) : "l"(v));
}
__device__ __forceinline__ uint32_t to_tf32(float v){
  uint32_t r; asm("cvt.rna.tf32.f32 %0, %1;" : "=r"(r) : "f"(v)); return r;
}

// ---- mma.sync m16n8k8 tf32 (baseline PTX, no arch-feature gate) ----
__device__ __forceinline__ void mma_tf32(float* c, const uint32_t* a, const uint32_t* b){
  asm volatile(
    "mma.sync.aligned.m16n8k8.row.col.f32.tf32.tf32.f32 "
    "{%0,%1,%2,%3}, {%4,%5,%6,%7}, {%8,%9}, {%0,%1,%2,%3};"
    : "+f"(c[0]), "+f"(c[1]), "+f"(c[2]), "+f"(c[3])
    : "r"(a[0]), "r"(a[1]), "r"(a[2]), "r"(a[3]), "r"(b[0]), "r"(b[1]));
}

// ---------------------------------------------------------------------------
// K0: transpose + TF32-round conv weights -> g_wT[branch][ci][tap][co]
// ---------------------------------------------------------------------------
__global__ void k_prep_w(const float* __restrict__ conv_w){
  int idx = blockIdx.x*256 + threadIdx.x;
  if (idx >= 2*64*9*64) return;
  int co  = idx & 63;
  int tap = (idx >> 6) % 9;
  int ci  = (idx / 576) & 63;
  int br  = idx / 36864;
  float v = conv_w[(co*128 + br*64 + ci)*9 + tap];
  g_wT[idx] = to_tf32(v);
}

// ---------------------------------------------------------------------------
// K1: 1x1 conv + BN + ReLU (FFMA2 path, fp32-exact; unchanged from R1)
// ---------------------------------------------------------------------------
__global__ __launch_bounds__(256) void k_pointwise(
    const float* __restrict__ x, const float* __restrict__ w,
    const float* __restrict__ gamma, const float* __restrict__ beta,
    const float* __restrict__ mean, const float* __restrict__ var,
    int sel)
{
  __shared__ float sw[64*64];   // [ci][co]
  float* out = sel ? g_vf : g_uf;
  int tid = threadIdx.x;
  for (int i = tid; i < 4096; i += 256){
    int ci = i >> 6, co = i & 63;
    sw[i] = w[co*64 + ci];
  }
  __syncthreads();

  int img  = blockIdx.y;
  int lane = tid & 63;
  int cg   = tid >> 6;
  int co0  = cg * 16;
  int pix  = blockIdx.x*256 + lane*4;
  const float* xi = x + (size_t)img*IMGSZ;

  ull acc[8][4];
  #pragma unroll
  for (int p=0;p<8;p++)
    #pragma unroll
    for (int j=0;j<4;j++) acc[p][j]=0ull;

  #pragma unroll 4
  for (int ci=0; ci<64; ++ci){
    float4 xv = *(const float4*)(xi + ci*HW + pix);
    ull x0=dup2(xv.x), x1=dup2(xv.y), x2=dup2(xv.z), x3=dup2(xv.w);
    const ulonglong2* wp = (const ulonglong2*)(sw + ci*64 + co0);
    ulonglong2 w0=wp[0], w1=wp[1], w2=wp[2], w3=wp[3];
    ull wv[8] = {w0.x,w0.y,w1.x,w1.y,w2.x,w2.y,w3.x,w3.y};
    #pragma unroll
    for (int p=0;p<8;p++){
      acc[p][0]=fma2(wv[p],x0,acc[p][0]);
      acc[p][1]=fma2(wv[p],x1,acc[p][1]);
      acc[p][2]=fma2(wv[p],x2,acc[p][2]);
      acc[p][3]=fma2(wv[p],x3,acc[p][3]);
    }
  }

  #pragma unroll
  for (int p=0;p<8;p++){
    int coa = co0 + 2*p, cob = coa + 1;
    float la = gamma[coa]*rsqrtf(var[coa]+1e-5f);
    float sa = beta[coa] - mean[coa]*la;
    float lb = gamma[cob]*rsqrtf(var[cob]+1e-5f);
    float sb = beta[cob] - mean[cob]*lb;
    float4 oa, ob;
    float lo, hi;
    unpk2(acc[p][0], lo, hi); oa.x=fmaxf(fmaf(lo,la,sa),0.f); ob.x=fmaxf(fmaf(hi,lb,sb),0.f);
    unpk2(acc[p][1], lo, hi); oa.y=fmaxf(fmaf(lo,la,sa),0.f); ob.y=fmaxf(fmaf(hi,lb,sb),0.f);
    unpk2(acc[p][2], lo, hi); oa.z=fmaxf(fmaf(lo,la,sa),0.f); ob.z=fmaxf(fmaf(hi,lb,sb),0.f);
    unpk2(acc[p][3], lo, hi); oa.w=fmaxf(fmaf(lo,la,sa),0.f); ob.w=fmaxf(fmaf(hi,lb,sb),0.f);
    *(float4*)(out + (size_t)(img*64+coa)*HW + pix) = oa;
    *(float4*)(out + (size_t)(img*64+cob)*HW + pix) = ob;
  }
}

// ---------------------------------------------------------------------------
// K2: 3x3 conv via mma.sync TF32 implicit GEMM.
// CTA: one image, tile 4h x 32w (M=128 pixels) x N=64 co.
// Warp grid 4(M) x 2(N): warp = 1 h-row (32 pixels) x 32 co.
// K = 8 ci-groups x 9 taps; A fragments gathered im2col-style from the raw
// padded input tile at LDS time (pitches chosen for conflict-free banks).
// ---------------------------------------------------------------------------
#define RAW_R   35       // row pitch within a ci slice (34 cols used)
#define RAW_CI  232      // ci pitch (232 % 32 == 8 -> conflict-free frags)
#define WPITCH  72       // co pitch for weight chunk (72 % 32 == 8)
#define SW_ELEMS (8*9*WPITCH)        // 5184
#define SMEM_SW_BYTES (SW_ELEMS*4)   // 20736
#define SMEM_RAW_BYTES (64*RAW_CI*4) // 59392
#define CONV_SMEM (SMEM_SW_BYTES + SMEM_RAW_BYTES)  // 80128

__global__ void __launch_bounds__(256, 2) k_conv_mma()
{
  extern __shared__ uint32_t S[];
  uint32_t* sw   = S;                         // [ci_l(8)][tap(9)][WPITCH]
  uint32_t* Sraw = S + SW_ELEMS;              // [ci(64)][RAW_CI]

  int tid  = threadIdx.x;
  int wid  = tid >> 5;
  int lane = tid & 31;
  int qid  = lane >> 2;      // 0..7
  int rid  = lane & 3;       // 0..3

  int bx  = blockIdx.x;
  int img = bx >> 7;               // 0..15
  int t   = bx & 127;
  int h0  = (t >> 2) << 2;
  int w0  = (t & 3) << 5;
  int wset = img >> 3;
  const float* in = (wset ? g_vf : g_uf) + (size_t)(img & 7)*IMGSZ;
  float* outp     = (wset ? g_ov : g_ou) + (size_t)(img & 7)*IMGSZ;

  // Stage raw input tile [64 ci][6 r][34 c], TF32-rounded, zero-padded borders
  for (int i = tid; i < 64*6*34; i += 256){
    int ci  = i / 204;
    int rem = i - ci*204;
    int r   = rem / 34;
    int cc  = rem - r*34;
    int gh  = h0 + r - 1;
    int gw  = w0 + cc - 1;
    float v = 0.f;
    if ((unsigned)gh < 128u && (unsigned)gw < 128u)
      v = __ldg(in + ci*HW + gh*128 + gw);
    Sraw[ci*RAW_CI + r*RAW_R + cc] = to_tf32(v);
  }

  int warpM = wid & 3;       // h row within tile
  int warpN = wid >> 2;      // 0/1 -> co0 = warpN*32
  int co0   = warpN << 5;

  float acc[2][4][4];
  #pragma unroll
  for (int a=0;a<2;a++)
    #pragma unroll
    for (int b=0;b<4;b++)
      #pragma unroll
      for (int e=0;e<4;e++) acc[a][b][e]=0.f;

  const uint32_t* wsrc = g_wT + (size_t)wset*36864;

  for (int cg = 0; cg < 8; ++cg){
    __syncthreads();
    // Stage weight chunk: ci in [cg*8, cg*8+8) -> sw[ci_l][tap][co] pitch 72
    {
      const uint32_t* src = wsrc + cg*8*576;
      for (int i = tid; i < 4608; i += 256){
        int ci_l = i / 576;
        int rem  = i - ci_l*576;
        int tap  = rem >> 6;
        int co   = rem & 63;
        sw[(ci_l*9 + tap)*WPITCH + co] = src[i];
      }
    }
    __syncthreads();

    // Per-thread base pointers for fragment gathers
    const uint32_t* Ab = Sraw + (cg*8 + rid)*RAW_CI + warpM*RAW_R + qid;
    const uint32_t* Bb = sw + rid*9*WPITCH + co0 + qid;

    #pragma unroll
    for (int tap = 0; tap < 9; ++tap){
      int ky = tap / 3;
      int kx = tap - ky*3;
      int aoff = ky*RAW_R + kx;

      uint32_t bfr[4][2];
      #pragma unroll
      for (int n8 = 0; n8 < 4; ++n8){
        bfr[n8][0] = Bb[tap*WPITCH + n8*8];
        bfr[n8][1] = Bb[tap*WPITCH + n8*8 + 4*9*WPITCH];
      }
      #pragma unroll
      for (int tt = 0; tt < 2; ++tt){
        uint32_t afr[4];
        const uint32_t* ap = Ab + aoff + tt*16;
        afr[0] = ap[0];
        afr[1] = ap[8];
        afr[2] = ap[4*RAW_CI];
        afr[3] = ap[4*RAW_CI + 8];
        #pragma unroll
        for (int n8 = 0; n8 < 4; ++n8)
          mma_tf32(acc[tt][n8], afr, bfr[n8]);
      }
    }
  }

  // Epilogue: scatter C fragments to gmem (co-major planes)
  int h = h0 + warpM;
  float* ob = outp + h*128 + w0;
  #pragma unroll
  for (int tt = 0; tt < 2; ++tt){
    int wbase = tt*16 + qid;
    #pragma unroll
    for (int n8 = 0; n8 < 4; ++n8){
      int coa = co0 + n8*8 + rid*2;
      ob[coa*HW + wbase]           = acc[tt][n8][0];
      ob[(coa+1)*HW + wbase]       = acc[tt][n8][1];
      ob[coa*HW + wbase + 8]       = acc[tt][n8][2];
      ob[(coa+1)*HW + wbase + 8]   = acc[tt][n8][3];
    }
  }
}

// ---------------------------------------------------------------------------
// K3: out[b,sx,sy,co,h,w] = ou[b*4+sx,co,h,w] + ov[b*4+sy,co,h,w] + bias[co]
// ---------------------------------------------------------------------------
__global__ void k_bcast_add(const float* __restrict__ bias, float* __restrict__ out){
  unsigned i = (blockIdx.x*256u + threadIdx.x)*4u;
  unsigned pix = i & 16383u;
  unsigned t = i >> 14;
  unsigned co = t & 63u;
  unsigned s  = t >> 6;
  unsigned sy = s & 3u;
  unsigned uimg = s >> 2;
  unsigned b  = uimg >> 2;
  unsigned vimg = b*4u + sy;
  float4 a = *(const float4*)(g_ou + (((size_t)(uimg*64u+co))<<14) + pix);
  float4 c = *(const float4*)(g_ov + (((size_t)(vimg*64u+co))<<14) + pix);
  float bi = __ldg(bias + co);
  float4 o;
  o.x = a.x + c.x + bi;
  o.y = a.y + c.y + bi;
  o.z = a.z + c.z + bi;
  o.w = a.w + c.w + bi;
  *(float4*)(out + i) = o;
}

// ---------------------------------------------------------------------------
extern "C" void kernel_launch(void* const* d_in, const int* in_sizes, int n_in,
                              void* d_out, int out_size)
{
  const float* u        = (const float*)d_in[0];
  const float* v        = (const float*)d_in[1];
  const float* pu_w     = (const float*)d_in[2];
  const float* pu_gamma = (const float*)d_in[3];
  const float* pu_beta  = (const float*)d_in[4];
  const float* pu_mean  = (const float*)d_in[5];
  const float* pu_var   = (const float*)d_in[6];
  const float* pv_w     = (const float*)d_in[7];
  const float* pv_gamma = (const float*)d_in[8];
  const float* pv_beta  = (const float*)d_in[9];
  const float* pv_mean  = (const float*)d_in[10];
  const float* pv_var   = (const float*)d_in[11];
  const float* conv_w   = (const float*)d_in[12];
  const float* conv_b   = (const float*)d_in[13];
  float* out = (float*)d_out;

  cudaFuncSetAttribute(k_conv_mma, cudaFuncAttributeMaxDynamicSharedMemorySize,
                       CONV_SMEM);

  k_prep_w<<<288, 256>>>(conv_w);

  dim3 pwg(64, 8);
  k_pointwise<<<pwg, 256>>>(u, pu_w, pu_gamma, pu_beta, pu_mean, pu_var, 0);
  k_pointwise<<<pwg, 256>>>(v, pv_w, pv_gamma, pv_beta, pv_mean, pv_var, 1);

  k_conv_mma<<<2048, 256, CONV_SMEM>>>();

  k_bcast_add<<<32768, 256>>>(conv_b, out);
}

// round 4
// speedup vs baseline: 1.7140x; 1.0295x over previous
#include <cuda_runtime.h>
#include <cstdint>

#define NIMG 8
#define HW 16384           // 128*128
#define IMGSZ (64*HW)

// Scratch (device globals)
__device__ float g_uf[NIMG*IMGSZ];
__device__ float g_vf[NIMG*IMGSZ];
__device__ float g_ou[NIMG*IMGSZ];
__device__ float g_ov[NIMG*IMGSZ];
// TF32-rounded transposed conv weights: [branch][ci(64)][tap(9)][co(64)]
__device__ uint32_t g_wT[2*64*9*64];

__device__ __forceinline__ uint32_t to_tf32(float v){
  uint32_t r; asm("cvt.rna.tf32.f32 %0, %1;" : "=r"(r) : "f"(v)); return r;
}
__device__ __forceinline__ void mma_tf32(float* c, const uint32_t* a, const uint32_t* b){
  asm volatile(
    "mma.sync.aligned.m16n8k8.row.col.f32.tf32.tf32.f32 "
    "{%0,%1,%2,%3}, {%4,%5,%6,%7}, {%8,%9}, {%0,%1,%2,%3};"
    : "+f"(c[0]), "+f"(c[1]), "+f"(c[2]), "+f"(c[3])
    : "r"(a[0]), "r"(a[1]), "r"(a[2]), "r"(a[3]), "r"(b[0]), "r"(b[1]));
}

// ---------------------------------------------------------------------------
// K0: transpose + TF32-round conv weights -> g_wT[branch][ci][tap][co]
// ---------------------------------------------------------------------------
__global__ void k_prep_w(const float* __restrict__ conv_w){
  int idx = blockIdx.x*256 + threadIdx.x;
  if (idx >= 2*64*9*64) return;
  int co  = idx & 63;
  int tap = (idx >> 6) % 9;
  int ci  = (idx / 576) & 63;
  int br  = idx / 36864;
  g_wT[idx] = to_tf32(conv_w[(co*128 + br*64 + ci)*9 + tap]);
}

// ---------------------------------------------------------------------------
// K1: 1x1 conv + BN + ReLU via TF32 mma.  D[64co x 256px] per CTA.
// A = W[co x ci] (row-major), B = X[ci x px] (col-major, coalesced staging).
// Warp = 64co x 32px. 8 warps -> 256 px per CTA. grid 512 per branch.
// ---------------------------------------------------------------------------
#define PW_AP 68
#define PW_XP 264
#define PW_AW (64*PW_AP)            // 4352 words
#define PW_XW (64*PW_XP)            // 16896 words
#define PW_SMEM ((PW_AW + PW_XW + 128)*4)   // 85504 B

__global__ void __launch_bounds__(256, 2) k_pw_mma(
    const float* __restrict__ x, const float* __restrict__ w,
    const float* __restrict__ gamma, const float* __restrict__ beta,
    const float* __restrict__ mean, const float* __restrict__ var,
    float* __restrict__ out)
{
  extern __shared__ uint32_t S[];
  uint32_t* sA = S;                       // [co][PW_AP]
  uint32_t* sX = S + PW_AW;               // [ci][PW_XP]
  float* sScale = (float*)(S + PW_AW + PW_XW);   // 64
  float* sShift = sScale + 64;                   // 64

  int tid  = threadIdx.x;
  int wid  = tid >> 5;
  int lane = tid & 31;
  int qid  = lane >> 2;
  int rid  = lane & 3;

  int img = blockIdx.x >> 6;
  int px0 = (blockIdx.x & 63) << 8;
  const float* xi = x + (size_t)img*IMGSZ + px0;

  // stage A (weights, tf32) as float4 rows
  for (int i = tid; i < 1024; i += 256){
    int co = i >> 4, ci4 = (i & 15) << 2;
    float4 v = *(const float4*)(w + co*64 + ci4);
    uint32_t* d = sA + co*PW_AP + ci4;
    d[0]=to_tf32(v.x); d[1]=to_tf32(v.y); d[2]=to_tf32(v.z); d[3]=to_tf32(v.w);
  }
  // stage scale/shift
  if (tid < 64){
    float la = gamma[tid]*rsqrtf(var[tid]+1e-5f);
    sScale[tid] = la;
    sShift[tid] = beta[tid] - mean[tid]*la;
  }
  // stage X coalesced: warp wid handles ci = wid*8..wid*8+7
  #pragma unroll
  for (int ci_l = 0; ci_l < 8; ++ci_l){
    int ci = wid*8 + ci_l;
    const float* p = xi + ci*HW;
    uint32_t* d = sX + ci*PW_XP;
    #pragma unroll
    for (int rep = 0; rep < 2; ++rep){
      int px = lane*4 + rep*128;
      float4 v = *(const float4*)(p + px);
      d[px]=to_tf32(v.x); d[px+1]=to_tf32(v.y); d[px+2]=to_tf32(v.z); d[px+3]=to_tf32(v.w);
    }
  }
  __syncthreads();

  int pw0 = wid << 5;
  float acc[4][4][4];
  #pragma unroll
  for (int t=0;t<4;t++)
    #pragma unroll
    for (int n=0;n<4;n++)
      #pragma unroll
      for (int e=0;e<4;e++) acc[t][n][e]=0.f;

  #pragma unroll
  for (int ks = 0; ks < 8; ++ks){
    int ci0 = ks*8;
    uint32_t bfr[4][2];
    #pragma unroll
    for (int n8 = 0; n8 < 4; ++n8){
      bfr[n8][0] = sX[(ci0+rid)*PW_XP   + pw0 + n8*8 + qid];
      bfr[n8][1] = sX[(ci0+rid+4)*PW_XP + pw0 + n8*8 + qid];
    }
    #pragma unroll
    for (int t = 0; t < 4; ++t){
      uint32_t afr[4];
      const uint32_t* ap = sA + (t*16 + qid)*PW_AP + ci0 + rid;
      afr[0] = ap[0];
      afr[1] = ap[8*PW_AP];
      afr[2] = ap[4];
      afr[3] = ap[8*PW_AP + 4];
      #pragma unroll
      for (int n8 = 0; n8 < 4; ++n8)
        mma_tf32(acc[t][n8], afr, bfr[n8]);
    }
  }

  // epilogue: BN + ReLU, write fp32 planes
  float* ob = out + (size_t)img*IMGSZ + px0 + pw0;
  #pragma unroll
  for (int t = 0; t < 4; ++t){
    int co0t = t*16 + qid;
    float la0 = sScale[co0t],   sa0 = sShift[co0t];
    float la1 = sScale[co0t+8], sa1 = sShift[co0t+8];
    #pragma unroll
    for (int n8 = 0; n8 < 4; ++n8){
      int pc = n8*8 + rid*2;
      float2 v0, v1;
      v0.x = fmaxf(fmaf(acc[t][n8][0], la0, sa0), 0.f);
      v0.y = fmaxf(fmaf(acc[t][n8][1], la0, sa0), 0.f);
      v1.x = fmaxf(fmaf(acc[t][n8][2], la1, sa1), 0.f);
      v1.y = fmaxf(fmaf(acc[t][n8][3], la1, sa1), 0.f);
      *(float2*)(ob + (size_t)co0t*HW + pc)     = v0;
      *(float2*)(ob + (size_t)(co0t+8)*HW + pc) = v1;
    }
  }
}

// ---------------------------------------------------------------------------
// K2: 3x3 conv via mma.sync TF32 implicit GEMM, v2.
// CTA: 256 px (8h x 32w) x 64 co, one image. Warp: 64 px x 32 co.
// Raw padded input tile [64ci][10r][35pitch], ci pitch 360 (conflict-free).
// Weights staged per 8-ci group: [8][9][72].
// ---------------------------------------------------------------------------
#define RAW_R 35
#define CIP   360
#define WP    72
#define RAW_W (64*CIP)               // 23040 words
#define SW_W  (8*9*WP)               // 5184 words
#define CONV_SMEM ((RAW_W + SW_W)*4) // 112896 B

__global__ void __launch_bounds__(256, 2) k_conv_mma()
{
  extern __shared__ uint32_t S[];
  uint32_t* Sraw = S;                 // [ci][CIP]
  uint32_t* sw   = S + RAW_W;         // [ci_l][tap][WP]

  int tid  = threadIdx.x;
  int wid  = tid >> 5;
  int lane = tid & 31;
  int qid  = lane >> 2;
  int rid  = lane & 3;

  int bx  = blockIdx.x;
  int img = bx >> 6;               // 0..15
  int t   = bx & 63;
  int h0  = (t >> 2) << 3;         // 16 h-tiles of 8
  int w0  = (t & 3)  << 5;         // 4 w-tiles of 32
  int wset = img >> 3;
  const float* in = (wset ? g_vf : g_uf) + (size_t)(img & 7)*IMGSZ;
  float* outp     = (wset ? g_ov : g_ou) + (size_t)(img & 7)*IMGSZ;

  // Stage raw tile: warp wid stages ci = wid*8 .. +7; rows h0-1..h0+8, cols w0-1..w0+32
  #pragma unroll
  for (int ci_l = 0; ci_l < 8; ++ci_l){
    int ci = wid*8 + ci_l;
    const float* p = in + ci*HW;
    uint32_t* dst = Sraw + ci*CIP;
    #pragma unroll
    for (int r = 0; r < 10; ++r){
      int gh = h0 + r - 1;
      bool vr = (unsigned)gh < 128u;
      int gw = w0 - 1 + lane;
      float v0 = (vr && (unsigned)gw < 128u) ? __ldg(p + gh*128 + gw) : 0.f;
      dst[r*RAW_R + lane] = to_tf32(v0);
      if (lane < 2){
        int gw2 = gw + 32;
        float v1 = (vr && (unsigned)gw2 < 128u) ? __ldg(p + gh*128 + gw2) : 0.f;
        dst[r*RAW_R + lane + 32] = to_tf32(v1);
      }
    }
  }

  int warpM = wid & 3;       // 2 h-rows each
  int co0   = (wid >> 2) << 5;

  float acc[4][4][4];
  #pragma unroll
  for (int a=0;a<4;a++)
    #pragma unroll
    for (int b=0;b<4;b++)
      #pragma unroll
      for (int e=0;e<4;e++) acc[a][b][e]=0.f;

  const float4* wsrc = (const float4*)(g_wT + (size_t)wset*36864);

  for (int cg = 0; cg < 8; ++cg){
    __syncthreads();
    // stage weight chunk [8ci][9tap][64co] -> pitch 72, float4
    {
      const float4* src = wsrc + cg*1152;
      for (int i = tid; i < 1152; i += 256){
        int ci_l = i / 144;
        int rem  = i - ci_l*144;
        int tap  = rem >> 4;
        int co4  = (rem & 15) << 2;
        *(float4*)(sw + (ci_l*9 + tap)*WP + co4) = __ldg(src + i);
      }
    }
    __syncthreads();

    const uint32_t* Ab = Sraw + (cg*8 + rid)*CIP + qid;
    const uint32_t* Bb = sw + rid*9*WP + co0 + qid;

    #pragma unroll
    for (int tap = 0; tap < 9; ++tap){
      int ky = tap / 3;
      int kx = tap - ky*3;

      uint32_t bfr[4][2];
      #pragma unroll
      for (int n8 = 0; n8 < 4; ++n8){
        bfr[n8][0] = Bb[tap*WP + n8*8];
        bfr[n8][1] = Bb[tap*WP + n8*8 + 4*9*WP];
      }
      #pragma unroll
      for (int tt = 0; tt < 4; ++tt){
        const uint32_t* ap = Ab + (warpM*2 + (tt>>1) + ky)*RAW_R + (tt&1)*16 + kx;
        uint32_t afr[4];
        afr[0] = ap[0];
        afr[1] = ap[8];
        afr[2] = ap[4*CIP];
        afr[3] = ap[4*CIP + 8];
        #pragma unroll
        for (int n8 = 0; n8 < 4; ++n8)
          mma_tf32(acc[tt][n8], afr, bfr[n8]);
      }
    }
  }

  // epilogue
  #pragma unroll
  for (int tt = 0; tt < 4; ++tt){
    int h  = h0 + warpM*2 + (tt>>1);
    int wc = w0 + (tt&1)*16 + qid;
    float* ob = outp + h*128 + wc;
    #pragma unroll
    for (int n8 = 0; n8 < 4; ++n8){
      int co = co0 + n8*8 + rid*2;
      ob[(size_t)co*HW]          = acc[tt][n8][0];
      ob[(size_t)(co+1)*HW]      = acc[tt][n8][1];
      ob[(size_t)co*HW + 8]      = acc[tt][n8][2];
      ob[(size_t)(co+1)*HW + 8]  = acc[tt][n8][3];
    }
  }
}

// ---------------------------------------------------------------------------
// K3: broadcast add with smem plane reuse.
// CTA = (b, co, blk): loads ou[4sx] + ov[4sy] planes (2048 px) into smem once,
// emits all 16 (sx,sy) outputs with streaming stores.
// ---------------------------------------------------------------------------
#define BC_PX 2048
#define BC_SMEM (8*BC_PX*4)    // 65536 B

__global__ void __launch_bounds__(256) k_bcast2(
    const float* __restrict__ bias, float* __restrict__ out)
{
  extern __shared__ float sm[];   // [8][BC_PX]: 0..3 = u(sx), 4..7 = v(sy)
  int tid = threadIdx.x;
  int blk = blockIdx.x;           // 0..7
  int co  = blockIdx.y;           // 0..63
  int b   = blockIdx.z;           // 0..1
  int px0 = blk*BC_PX;

  #pragma unroll
  for (int s = 0; s < 4; ++s){
    const float* pu = g_ou + (((size_t)((b*4+s)*64 + co))<<14) + px0;
    const float* pv = g_ov + (((size_t)((b*4+s)*64 + co))<<14) + px0;
    #pragma unroll
    for (int rep = 0; rep < 2; ++rep){
      int j = tid*4 + rep*1024;
      *(float4*)(sm + s*BC_PX + j)     = __ldcs((const float4*)(pu + j));
      *(float4*)(sm + (4+s)*BC_PX + j) = __ldcs((const float4*)(pv + j));
    }
  }
  __syncthreads();

  float bi = __ldg(bias + co);
  #pragma unroll
  for (int sx = 0; sx < 4; ++sx){
    #pragma unroll
    for (int sy = 0; sy < 4; ++sy){
      float* op = out + (((size_t)((((b*4+sx)*4+sy)*64)+co))<<14) + px0;
      #pragma unroll
      for (int rep = 0; rep < 2; ++rep){
        int j = tid*4 + rep*1024;
        float4 a = *(float4*)(sm + sx*BC_PX + j);
        float4 c = *(float4*)(sm + (4+sy)*BC_PX + j);
        float4 o;
        o.x = a.x + c.x + bi;
        o.y = a.y + c.y + bi;
        o.z = a.z + c.z + bi;
        o.w = a.w + c.w + bi;
        __stcs((float4*)(op + j), o);
      }
    }
  }
}

// ---------------------------------------------------------------------------
extern "C" void kernel_launch(void* const* d_in, const int* in_sizes, int n_in,
                              void* d_out, int out_size)
{
  const float* u        = (const float*)d_in[0];
  const float* v        = (const float*)d_in[1];
  const float* pu_w     = (const float*)d_in[2];
  const float* pu_gamma = (const float*)d_in[3];
  const float* pu_beta  = (const float*)d_in[4];
  const float* pu_mean  = (const float*)d_in[5];
  const float* pu_var   = (const float*)d_in[6];
  const float* pv_w     = (const float*)d_in[7];
  const float* pv_gamma = (const float*)d_in[8];
  const float* pv_beta  = (const float*)d_in[9];
  const float* pv_mean  = (const float*)d_in[10];
  const float* pv_var   = (const float*)d_in[11];
  const float* conv_w   = (const float*)d_in[12];
  const float* conv_b   = (const float*)d_in[13];
  float* out = (float*)d_out;

  static int attr_set = 0;
  if (!attr_set){
    cudaFuncSetAttribute(k_pw_mma,   cudaFuncAttributeMaxDynamicSharedMemorySize, PW_SMEM);
    cudaFuncSetAttribute(k_conv_mma, cudaFuncAttributeMaxDynamicSharedMemorySize, CONV_SMEM);
    cudaFuncSetAttribute(k_bcast2,   cudaFuncAttributeMaxDynamicSharedMemorySize, BC_SMEM);
    attr_set = 1;
  }

  k_prep_w<<<288, 256>>>(conv_w);

  float* g_uf_p; cudaGetSymbolAddress((void**)&g_uf_p, g_uf);
  float* g_vf_p; cudaGetSymbolAddress((void**)&g_vf_p, g_vf);

  k_pw_mma<<<512, 256, PW_SMEM>>>(u, pu_w, pu_gamma, pu_beta, pu_mean, pu_var, g_uf_p);
  k_pw_mma<<<512, 256, PW_SMEM>>>(v, pv_w, pv_gamma, pv_beta, pv_mean, pv_var, g_vf_p);

  k_conv_mma<<<1024, 256, CONV_SMEM>>>();

  dim3 bg(8, 64, 2);
  k_bcast2<<<bg, 256, BC_SMEM>>>(conv_b, out);
}

// round 5
// speedup vs baseline: 1.7534x; 1.0230x over previous
#include <cuda_runtime.h>
#include <cstdint>

#define NIMG 8
#define HW 16384           // 128*128
#define IMGSZ (64*HW)

// Scratch (device globals)
__device__ float g_uf[NIMG*IMGSZ];   // tf32-pre-rounded activations
__device__ float g_vf[NIMG*IMGSZ];
__device__ float g_ou[NIMG*IMGSZ];
__device__ float g_ov[NIMG*IMGSZ];
// Paired TF32 conv weights: [branch][cg(8)][tap(9)][co(64)][rid(4)][2]
// pair p: ci = cg*8 + rid + p*4
__device__ uint32_t g_wP[2*8*9*64*4*2];

__device__ __forceinline__ uint32_t to_tf32(float v){
  uint32_t r; asm("cvt.rna.tf32.f32 %0, %1;" : "=r"(r) : "f"(v)); return r;
}
__device__ __forceinline__ void mma_tf32(float* c, const uint32_t* a, const uint32_t* b){
  asm volatile(
    "mma.sync.aligned.m16n8k8.row.col.f32.tf32.tf32.f32 "
    "{%0,%1,%2,%3}, {%4,%5,%6,%7}, {%8,%9}, {%0,%1,%2,%3};"
    : "+f"(c[0]), "+f"(c[1]), "+f"(c[2]), "+f"(c[3])
    : "r"(a[0]), "r"(a[1]), "r"(a[2]), "r"(a[3]), "r"(b[0]), "r"(b[1]));
}
__device__ __forceinline__ uint32_t smem_u32(const void* p){
  uint32_t a;
  asm("{ .reg .u64 t; cvta.to.shared.u64 t, %1; cvt.u32.u64 %0, t; }" : "=r"(a) : "l"(p));
  return a;
}
__device__ __forceinline__ void cp_async16(uint32_t saddr, const void* gptr){
  asm volatile("cp.async.ca.shared.global [%0], [%1], 16;" :: "r"(saddr), "l"(gptr));
}

// ---------------------------------------------------------------------------
// K0: build paired TF32 weights  g_wP[br][cg][tap][co][rid][p]
// ---------------------------------------------------------------------------
__global__ void k_prep_w(const float* __restrict__ conv_w){
  int idx = blockIdx.x*256 + threadIdx.x;   // 73728 total
  int p   = idx & 1;
  int rid = (idx >> 1) & 3;
  int co  = (idx >> 3) & 63;
  int tap = (idx >> 9) % 9;
  int t2  = (idx >> 9) / 9;
  int cg  = t2 & 7;
  int br  = t2 >> 3;
  int ci  = cg*8 + rid + p*4;
  g_wP[idx] = to_tf32(conv_w[(co*128 + br*64 + ci)*9 + tap]);
}

// ---------------------------------------------------------------------------
// K1: 1x1 conv + BN + ReLU via TF32 mma. Outputs tf32-pre-rounded floats.
// ---------------------------------------------------------------------------
#define PW_AP 68
#define PW_XP 264
#define PW_AW (64*PW_AP)
#define PW_XW (64*PW_XP)
#define PW_SMEM ((PW_AW + PW_XW + 128)*4)

__global__ void __launch_bounds__(256, 2) k_pw_mma(
    const float* __restrict__ x, const float* __restrict__ w,
    const float* __restrict__ gamma, const float* __restrict__ beta,
    const float* __restrict__ mean, const float* __restrict__ var,
    float* __restrict__ out)
{
  extern __shared__ uint32_t S[];
  uint32_t* sA = S;                       // [co][PW_AP]
  uint32_t* sX = S + PW_AW;               // [ci][PW_XP]
  float* sScale = (float*)(S + PW_AW + PW_XW);
  float* sShift = sScale + 64;

  int tid  = threadIdx.x;
  int wid  = tid >> 5;
  int lane = tid & 31;
  int qid  = lane >> 2;
  int rid  = lane & 3;

  int img = blockIdx.x >> 6;
  int px0 = (blockIdx.x & 63) << 8;
  const float* xi = x + (size_t)img*IMGSZ + px0;

  for (int i = tid; i < 1024; i += 256){
    int co = i >> 4, ci4 = (i & 15) << 2;
    float4 v = *(const float4*)(w + co*64 + ci4);
    uint32_t* d = sA + co*PW_AP + ci4;
    d[0]=to_tf32(v.x); d[1]=to_tf32(v.y); d[2]=to_tf32(v.z); d[3]=to_tf32(v.w);
  }
  if (tid < 64){
    float la = gamma[tid]*rsqrtf(var[tid]+1e-5f);
    sScale[tid] = la;
    sShift[tid] = beta[tid] - mean[tid]*la;
  }
  #pragma unroll
  for (int ci_l = 0; ci_l < 8; ++ci_l){
    int ci = wid*8 + ci_l;
    const float* p = xi + ci*HW;
    uint32_t* d = sX + ci*PW_XP;
    #pragma unroll
    for (int rep = 0; rep < 2; ++rep){
      int px = lane*4 + rep*128;
      float4 v = *(const float4*)(p + px);
      d[px]=to_tf32(v.x); d[px+1]=to_tf32(v.y); d[px+2]=to_tf32(v.z); d[px+3]=to_tf32(v.w);
    }
  }
  __syncthreads();

  int pw0 = wid << 5;
  float acc[4][4][4];
  #pragma unroll
  for (int t=0;t<4;t++)
    #pragma unroll
    for (int n=0;n<4;n++)
      #pragma unroll
      for (int e=0;e<4;e++) acc[t][n][e]=0.f;

  #pragma unroll
  for (int ks = 0; ks < 8; ++ks){
    int ci0 = ks*8;
    uint32_t bfr[4][2];
    #pragma unroll
    for (int n8 = 0; n8 < 4; ++n8){
      bfr[n8][0] = sX[(ci0+rid)*PW_XP   + pw0 + n8*8 + qid];
      bfr[n8][1] = sX[(ci0+rid+4)*PW_XP + pw0 + n8*8 + qid];
    }
    #pragma unroll
    for (int t = 0; t < 4; ++t){
      uint32_t afr[4];
      const uint32_t* ap = sA + (t*16 + qid)*PW_AP + ci0 + rid;
      afr[0] = ap[0];
      afr[1] = ap[8*PW_AP];
      afr[2] = ap[4];
      afr[3] = ap[8*PW_AP + 4];
      #pragma unroll
      for (int n8 = 0; n8 < 4; ++n8)
        mma_tf32(acc[t][n8], afr, bfr[n8]);
    }
  }

  // epilogue: BN + ReLU + tf32 pre-round (conv consumes these)
  float* ob = out + (size_t)img*IMGSZ + px0 + pw0;
  #pragma unroll
  for (int t = 0; t < 4; ++t){
    int co0t = t*16 + qid;
    float la0 = sScale[co0t],   sa0 = sShift[co0t];
    float la1 = sScale[co0t+8], sa1 = sShift[co0t+8];
    #pragma unroll
    for (int n8 = 0; n8 < 4; ++n8){
      int pc = n8*8 + rid*2;
      uint2 v0, v1;
      v0.x = to_tf32(fmaxf(fmaf(acc[t][n8][0], la0, sa0), 0.f));
      v0.y = to_tf32(fmaxf(fmaf(acc[t][n8][1], la0, sa0), 0.f));
      v1.x = to_tf32(fmaxf(fmaf(acc[t][n8][2], la1, sa1), 0.f));
      v1.y = to_tf32(fmaxf(fmaf(acc[t][n8][3], la1, sa1), 0.f));
      *(uint2*)(ob + (size_t)co0t*HW + pc)     = v0;
      *(uint2*)(ob + (size_t)(co0t+8)*HW + pc) = v1;
    }
  }
}

// ---------------------------------------------------------------------------
// K2: 3x3 conv, mma.sync TF32, v3.
// CTA: 128 px (4h x 32w) x 64 co, one image (2048 CTAs).
// Warp: 32 px (1 h-row) x 32 co; acc = 32 regs.
// Weight chunks (per 8-ci cg, paired layout) double-buffered via cp.async.
// ---------------------------------------------------------------------------
#define RAW_R 35
#define CIP   232                    // %32==8 -> conflict-free A frags
#define SWW   4608                   // words per weight chunk [9][64][4][2]
#define RAWW  (64*CIP)               // 14848 words
#define CONV_SMEM ((2*SWW + RAWW)*4) // 96256 B

__global__ void __launch_bounds__(256, 2) k_conv_mma()
{
  extern __shared__ uint32_t S[];
  uint32_t* swb  = S;                // two buffers of SWW
  uint32_t* Sraw = S + 2*SWW;        // [ci][CIP] (rows 0..5 x 35)

  int tid  = threadIdx.x;
  int wid  = tid >> 5;
  int lane = tid & 31;
  int qid  = lane >> 2;
  int rid  = lane & 3;

  int bx  = blockIdx.x;
  int img = bx >> 7;               // 0..15
  int t   = bx & 127;
  int h0  = (t >> 2) << 2;
  int w0  = (t & 3)  << 5;
  int wset = img >> 3;
  const float* in = (wset ? g_vf : g_uf) + (size_t)(img & 7)*IMGSZ;
  float* outp     = (wset ? g_ov : g_ou) + (size_t)(img & 7)*IMGSZ;

  const uint32_t* wsrc = g_wP + (size_t)wset*36864;

  // prefetch weight chunk cg=0 into buf0
  {
    uint32_t dst = smem_u32(swb);
    #pragma unroll
    for (int i = 0; i < 5; ++i){
      int j = tid + i*256;
      if (j < 1152) cp_async16(dst + j*16, wsrc + j*4);
    }
    asm volatile("cp.async.commit_group;");
  }

  // stage raw input tile (activations already tf32-rounded; raw copy)
  #pragma unroll
  for (int ci_l = 0; ci_l < 8; ++ci_l){
    int ci = wid*8 + ci_l;
    const uint32_t* p = (const uint32_t*)(in + ci*HW);
    uint32_t* dst = Sraw + ci*CIP;
    #pragma unroll
    for (int r = 0; r < 6; ++r){
      int gh = h0 + r - 1;
      bool vr = (unsigned)gh < 128u;
      int gw = w0 - 1 + lane;
      uint32_t v0 = (vr && (unsigned)gw < 128u) ? __ldg(p + gh*128 + gw) : 0u;
      dst[r*RAW_R + lane] = v0;
      if (lane < 2){
        int gw2 = gw + 32;
        uint32_t v1 = (vr && (unsigned)gw2 < 128u) ? __ldg(p + gh*128 + gw2) : 0u;
        dst[r*RAW_R + lane + 32] = v1;
      }
    }
  }

  asm volatile("cp.async.wait_group 0;");
  __syncthreads();

  int warpM = wid & 3;
  int co0   = (wid >> 2) << 5;

  float acc[2][4][4];
  #pragma unroll
  for (int a=0;a<2;a++)
    #pragma unroll
    for (int b=0;b<4;b++)
      #pragma unroll
      for (int e=0;e<4;e++) acc[a][b][e]=0.f;

  for (int cg = 0; cg < 8; ++cg){
    int cur = cg & 1;
    // prefetch next chunk
    if (cg < 7){
      uint32_t dst = smem_u32(swb + (cur^1)*SWW);
      const uint32_t* src = wsrc + (cg+1)*SWW;
      #pragma unroll
      for (int i = 0; i < 5; ++i){
        int j = tid + i*256;
        if (j < 1152) cp_async16(dst + j*16, src + j*4);
      }
      asm volatile("cp.async.commit_group;");
    }

    const uint32_t* Ab = Sraw + (cg*8 + rid)*CIP + warpM*RAW_R + qid;
    // B base: [tap][co][rid][2] ; thread: co = co0 + n8*8 + qid
    const uint2* Bb = (const uint2*)(swb + cur*SWW) + (co0 + qid)*4 + rid;

    #pragma unroll
    for (int tap = 0; tap < 9; ++tap){
      int ky = tap / 3;
      int kx = tap - ky*3;
      int aoff = ky*RAW_R + kx;

      uint32_t bfr[4][2];
      #pragma unroll
      for (int n8 = 0; n8 < 4; ++n8){
        uint2 bp = Bb[tap*256 + n8*32];
        bfr[n8][0] = bp.x;
        bfr[n8][1] = bp.y;
      }
      #pragma unroll
      for (int tt = 0; tt < 2; ++tt){
        const uint32_t* ap = Ab + aoff + tt*16;
        uint32_t afr[4];
        afr[0] = ap[0];
        afr[1] = ap[8];
        afr[2] = ap[4*CIP];
        afr[3] = ap[4*CIP + 8];
        #pragma unroll
        for (int n8 = 0; n8 < 4; ++n8)
          mma_tf32(acc[tt][n8], afr, bfr[n8]);
      }
    }

    asm volatile("cp.async.wait_group 0;");
    __syncthreads();
  }

  // epilogue
  int h = h0 + warpM;
  float* ob = outp + h*128 + w0;
  #pragma unroll
  for (int tt = 0; tt < 2; ++tt){
    int wbase = tt*16 + qid;
    #pragma unroll
    for (int n8 = 0; n8 < 4; ++n8){
      int co = co0 + n8*8 + rid*2;
      ob[(size_t)co*HW + wbase]          = acc[tt][n8][0];
      ob[(size_t)(co+1)*HW + wbase]      = acc[tt][n8][1];
      ob[(size_t)co*HW + wbase + 8]      = acc[tt][n8][2];
      ob[(size_t)(co+1)*HW + wbase + 8]  = acc[tt][n8][3];
    }
  }
}

// ---------------------------------------------------------------------------
// K3: broadcast add with smem plane reuse.
// ---------------------------------------------------------------------------
#define BC_PX 2048
#define BC_SMEM (8*BC_PX*4)

__global__ void __launch_bounds__(256) k_bcast2(
    const float* __restrict__ bias, float* __restrict__ out)
{
  extern __shared__ float sm[];
  int tid = threadIdx.x;
  int blk = blockIdx.x;
  int co  = blockIdx.y;
  int b   = blockIdx.z;
  int px0 = blk*BC_PX;

  #pragma unroll
  for (int s = 0; s < 4; ++s){
    const float* pu = g_ou + (((size_t)((b*4+s)*64 + co))<<14) + px0;
    const float* pv = g_ov + (((size_t)((b*4+s)*64 + co))<<14) + px0;
    #pragma unroll
    for (int rep = 0; rep < 2; ++rep){
      int j = tid*4 + rep*1024;
      *(float4*)(sm + s*BC_PX + j)     = __ldcs((const float4*)(pu + j));
      *(float4*)(sm + (4+s)*BC_PX + j) = __ldcs((const float4*)(pv + j));
    }
  }
  __syncthreads();

  float bi = __ldg(bias + co);
  #pragma unroll
  for (int sx = 0; sx < 4; ++sx){
    #pragma unroll
    for (int sy = 0; sy < 4; ++sy){
      float* op = out + (((size_t)((((b*4+sx)*4+sy)*64)+co))<<14) + px0;
      #pragma unroll
      for (int rep = 0; rep < 2; ++rep){
        int j = tid*4 + rep*1024;
        float4 a = *(float4*)(sm + sx*BC_PX + j);
        float4 c = *(float4*)(sm + (4+sy)*BC_PX + j);
        float4 o;
        o.x = a.x + c.x + bi;
        o.y = a.y + c.y + bi;
        o.z = a.z + c.z + bi;
        o.w = a.w + c.w + bi;
        __stcs((float4*)(op + j), o);
      }
    }
  }
}

// ---------------------------------------------------------------------------
extern "C" void kernel_launch(void* const* d_in, const int* in_sizes, int n_in,
                              void* d_out, int out_size)
{
  const float* u        = (const float*)d_in[0];
  const float* v        = (const float*)d_in[1];
  const float* pu_w     = (const float*)d_in[2];
  const float* pu_gamma = (const float*)d_in[3];
  const float* pu_beta  = (const float*)d_in[4];
  const float* pu_mean  = (const float*)d_in[5];
  const float* pu_var   = (const float*)d_in[6];
  const float* pv_w     = (const float*)d_in[7];
  const float* pv_gamma = (const float*)d_in[8];
  const float* pv_beta  = (const float*)d_in[9];
  const float* pv_mean  = (const float*)d_in[10];
  const float* pv_var   = (const float*)d_in[11];
  const float* conv_w   = (const float*)d_in[12];
  const float* conv_b   = (const float*)d_in[13];
  float* out = (float*)d_out;

  static int attr_set = 0;
  if (!attr_set){
    cudaFuncSetAttribute(k_pw_mma,   cudaFuncAttributeMaxDynamicSharedMemorySize, PW_SMEM);
    cudaFuncSetAttribute(k_conv_mma, cudaFuncAttributeMaxDynamicSharedMemorySize, CONV_SMEM);
    cudaFuncSetAttribute(k_bcast2,   cudaFuncAttributeMaxDynamicSharedMemorySize, BC_SMEM);
    attr_set = 1;
  }

  k_prep_w<<<288, 256>>>(conv_w);

  float* g_uf_p; cudaGetSymbolAddress((void**)&g_uf_p, g_uf);
  float* g_vf_p; cudaGetSymbolAddress((void**)&g_vf_p, g_vf);

  k_pw_mma<<<512, 256, PW_SMEM>>>(u, pu_w, pu_gamma, pu_beta, pu_mean, pu_var, g_uf_p);
  k_pw_mma<<<512, 256, PW_SMEM>>>(v, pv_w, pv_gamma, pv_beta, pv_mean, pv_var, g_vf_p);

  k_conv_mma<<<2048, 256, CONV_SMEM>>>();

  dim3 bg(8, 64, 2);
  k_bcast2<<<bg, 256, BC_SMEM>>>(conv_b, out);
}

// round 6
// speedup vs baseline: 1.7834x; 1.0171x over previous
#include <cuda_runtime.h>
#include <cstdint>

#define NIMG 8
#define HW 16384           // 128*128
#define IMGSZ (64*HW)

// Scratch (device globals)
__device__ float g_uf[NIMG*IMGSZ];   // tf32-pre-rounded activations
__device__ float g_vf[NIMG*IMGSZ];
__device__ float g_ou[NIMG*IMGSZ];
__device__ float g_ov[NIMG*IMGSZ];
// Paired TF32 conv weights: [branch][cg(8)][tap(9)][co(64)][rid(4)][2]
// pair p: ci = cg*8 + rid + p*4
__device__ uint32_t g_wP[2*8*9*64*4*2];

__device__ __forceinline__ uint32_t to_tf32(float v){
  uint32_t r; asm("cvt.rna.tf32.f32 %0, %1;" : "=r"(r) : "f"(v)); return r;
}
__device__ __forceinline__ void mma_tf32(float* c, const uint32_t* a, const uint32_t* b){
  asm volatile(
    "mma.sync.aligned.m16n8k8.row.col.f32.tf32.tf32.f32 "
    "{%0,%1,%2,%3}, {%4,%5,%6,%7}, {%8,%9}, {%0,%1,%2,%3};"
    : "+f"(c[0]), "+f"(c[1]), "+f"(c[2]), "+f"(c[3])
    : "r"(a[0]), "r"(a[1]), "r"(a[2]), "r"(a[3]), "r"(b[0]), "r"(b[1]));
}
__device__ __forceinline__ uint32_t smem_u32(const void* p){
  uint32_t a;
  asm("{ .reg .u64 t; cvta.to.shared.u64 t, %1; cvt.u32.u64 %0, t; }" : "=r"(a) : "l"(p));
  return a;
}
__device__ __forceinline__ void cp_async16(uint32_t saddr, const void* gptr){
  asm volatile("cp.async.ca.shared.global [%0], [%1], 16;" :: "r"(saddr), "l"(gptr));
}

// ---------------------------------------------------------------------------
// K0: build paired TF32 weights  g_wP[br][cg][tap][co][rid][p]
// ---------------------------------------------------------------------------
__global__ void k_prep_w(const float* __restrict__ conv_w){
  int idx = blockIdx.x*256 + threadIdx.x;   // 73728 total
  int p   = idx & 1;
  int rid = (idx >> 1) & 3;
  int co  = (idx >> 3) & 63;
  int tap = (idx >> 9) % 9;
  int t2  = (idx >> 9) / 9;
  int cg  = t2 & 7;
  int br  = t2 >> 3;
  int ci  = cg*8 + rid + p*4;
  g_wP[idx] = to_tf32(conv_w[(co*128 + br*64 + ci)*9 + tap]);
}

// ---------------------------------------------------------------------------
// K1: 1x1 conv + BN + ReLU via TF32 mma. Outputs tf32-pre-rounded floats.
// ---------------------------------------------------------------------------
#define PW_AP 68
#define PW_XP 264
#define PW_AW (64*PW_AP)
#define PW_XW (64*PW_XP)
#define PW_SMEM ((PW_AW + PW_XW + 128)*4)

__global__ void __launch_bounds__(256, 2) k_pw_mma(
    const float* __restrict__ x, const float* __restrict__ w,
    const float* __restrict__ gamma, const float* __restrict__ beta,
    const float* __restrict__ mean, const float* __restrict__ var,
    float* __restrict__ out)
{
  extern __shared__ uint32_t S[];
  uint32_t* sA = S;                       // [co][PW_AP]
  uint32_t* sX = S + PW_AW;               // [ci][PW_XP]
  float* sScale = (float*)(S + PW_AW + PW_XW);
  float* sShift = sScale + 64;

  int tid  = threadIdx.x;
  int wid  = tid >> 5;
  int lane = tid & 31;
  int qid  = lane >> 2;
  int rid  = lane & 3;

  int img = blockIdx.x >> 6;
  int px0 = (blockIdx.x & 63) << 8;
  const float* xi = x + (size_t)img*IMGSZ + px0;

  for (int i = tid; i < 1024; i += 256){
    int co = i >> 4, ci4 = (i & 15) << 2;
    float4 v = *(const float4*)(w + co*64 + ci4);
    uint32_t* d = sA + co*PW_AP + ci4;
    d[0]=to_tf32(v.x); d[1]=to_tf32(v.y); d[2]=to_tf32(v.z); d[3]=to_tf32(v.w);
  }
  if (tid < 64){
    float la = gamma[tid]*rsqrtf(var[tid]+1e-5f);
    sScale[tid] = la;
    sShift[tid] = beta[tid] - mean[tid]*la;
  }
  #pragma unroll
  for (int ci_l = 0; ci_l < 8; ++ci_l){
    int ci = wid*8 + ci_l;
    const float* p = xi + ci*HW;
    uint32_t* d = sX + ci*PW_XP;
    #pragma unroll
    for (int rep = 0; rep < 2; ++rep){
      int px = lane*4 + rep*128;
      float4 v = *(const float4*)(p + px);
      d[px]=to_tf32(v.x); d[px+1]=to_tf32(v.y); d[px+2]=to_tf32(v.z); d[px+3]=to_tf32(v.w);
    }
  }
  __syncthreads();

  int pw0 = wid << 5;
  float acc[4][4][4];
  #pragma unroll
  for (int t=0;t<4;t++)
    #pragma unroll
    for (int n=0;n<4;n++)
      #pragma unroll
      for (int e=0;e<4;e++) acc[t][n][e]=0.f;

  #pragma unroll
  for (int ks = 0; ks < 8; ++ks){
    int ci0 = ks*8;
    uint32_t bfr[4][2];
    #pragma unroll
    for (int n8 = 0; n8 < 4; ++n8){
      bfr[n8][0] = sX[(ci0+rid)*PW_XP   + pw0 + n8*8 + qid];
      bfr[n8][1] = sX[(ci0+rid+4)*PW_XP + pw0 + n8*8 + qid];
    }
    #pragma unroll
    for (int t = 0; t < 4; ++t){
      uint32_t afr[4];
      const uint32_t* ap = sA + (t*16 + qid)*PW_AP + ci0 + rid;
      afr[0] = ap[0];
      afr[1] = ap[8*PW_AP];
      afr[2] = ap[4];
      afr[3] = ap[8*PW_AP + 4];
      #pragma unroll
      for (int n8 = 0; n8 < 4; ++n8)
        mma_tf32(acc[t][n8], afr, bfr[n8]);
    }
  }

  // epilogue: BN + ReLU + tf32 pre-round (conv consumes these)
  float* ob = out + (size_t)img*IMGSZ + px0 + pw0;
  #pragma unroll
  for (int t = 0; t < 4; ++t){
    int co0t = t*16 + qid;
    float la0 = sScale[co0t],   sa0 = sShift[co0t];
    float la1 = sScale[co0t+8], sa1 = sShift[co0t+8];
    #pragma unroll
    for (int n8 = 0; n8 < 4; ++n8){
      int pc = n8*8 + rid*2;
      uint2 v0, v1;
      v0.x = to_tf32(fmaxf(fmaf(acc[t][n8][0], la0, sa0), 0.f));
      v0.y = to_tf32(fmaxf(fmaf(acc[t][n8][1], la0, sa0), 0.f));
      v1.x = to_tf32(fmaxf(fmaf(acc[t][n8][2], la1, sa1), 0.f));
      v1.y = to_tf32(fmaxf(fmaf(acc[t][n8][3], la1, sa1), 0.f));
      *(uint2*)(ob + (size_t)co0t*HW + pc)     = v0;
      *(uint2*)(ob + (size_t)(co0t+8)*HW + pc) = v1;
    }
  }
}

// ---------------------------------------------------------------------------
// K2: 3x3 conv, mma.sync TF32, v4: register-pipelined fragments across taps.
// CTA: 128 px (4h x 32w) x 64 co, one image (2048 CTAs).
// Warp: 32 px (1 h-row) x 32 co; acc = 32 regs + 2x16 frag regs.
// Weight chunks double-buffered in smem via cp.async.
// ---------------------------------------------------------------------------
#define RAW_R 35
#define CIP   232                    // %32==8 -> conflict-free A frags
#define SWW   4608                   // words per weight chunk [9][64][4][2]
#define RAWW  (64*CIP)               // 14848 words
#define CONV_SMEM ((2*SWW + RAWW)*4) // 96256 B

__global__ void __launch_bounds__(256, 2) k_conv_mma()
{
  extern __shared__ uint32_t S[];
  uint32_t* swb  = S;                // two buffers of SWW
  uint32_t* Sraw = S + 2*SWW;        // [ci][CIP] (rows 0..5 x 35)

  int tid  = threadIdx.x;
  int wid  = tid >> 5;
  int lane = tid & 31;
  int qid  = lane >> 2;
  int rid  = lane & 3;

  int bx  = blockIdx.x;
  int img = bx >> 7;               // 0..15
  int t   = bx & 127;
  int h0  = (t >> 2) << 2;
  int w0  = (t & 3)  << 5;
  int wset = img >> 3;
  const float* in = (wset ? g_vf : g_uf) + (size_t)(img & 7)*IMGSZ;
  float* outp     = (wset ? g_ov : g_ou) + (size_t)(img & 7)*IMGSZ;

  const uint32_t* wsrc = g_wP + (size_t)wset*36864;

  // prefetch weight chunk cg=0 into buf0
  {
    uint32_t dst = smem_u32(swb);
    #pragma unroll
    for (int i = 0; i < 5; ++i){
      int j = tid + i*256;
      if (j < 1152) cp_async16(dst + j*16, wsrc + j*4);
    }
    asm volatile("cp.async.commit_group;");
  }

  // stage raw input tile (activations already tf32-rounded; raw copy)
  #pragma unroll
  for (int ci_l = 0; ci_l < 8; ++ci_l){
    int ci = wid*8 + ci_l;
    const uint32_t* p = (const uint32_t*)(in + ci*HW);
    uint32_t* dst = Sraw + ci*CIP;
    #pragma unroll
    for (int r = 0; r < 6; ++r){
      int gh = h0 + r - 1;
      bool vr = (unsigned)gh < 128u;
      int gw = w0 - 1 + lane;
      uint32_t v0 = (vr && (unsigned)gw < 128u) ? __ldg(p + gh*128 + gw) : 0u;
      dst[r*RAW_R + lane] = v0;
      if (lane < 2){
        int gw2 = gw + 32;
        uint32_t v1 = (vr && (unsigned)gw2 < 128u) ? __ldg(p + gh*128 + gw2) : 0u;
        dst[r*RAW_R + lane + 32] = v1;
      }
    }
  }

  asm volatile("cp.async.wait_group 0;");
  __syncthreads();

  int warpM = wid & 3;
  int co0   = (wid >> 2) << 5;

  float acc[2][4][4];
  #pragma unroll
  for (int a=0;a<2;a++)
    #pragma unroll
    for (int b=0;b<4;b++)
      #pragma unroll
      for (int e=0;e<4;e++) acc[a][b][e]=0.f;

  for (int cg = 0; cg < 8; ++cg){
    int cur = cg & 1;
    // prefetch next weight chunk into the other buffer
    if (cg < 7){
      uint32_t dst = smem_u32(swb + (cur^1)*SWW);
      const uint32_t* src = wsrc + (cg+1)*SWW;
      #pragma unroll
      for (int i = 0; i < 5; ++i){
        int j = tid + i*256;
        if (j < 1152) cp_async16(dst + j*16, src + j*4);
      }
      asm volatile("cp.async.commit_group;");
    }

    const uint32_t* Ab = Sraw + (cg*8 + rid)*CIP + warpM*RAW_R + qid;
    const uint2* Bb = (const uint2*)(swb + cur*SWW) + (co0 + qid)*4 + rid;

    // ---- register-pipelined tap loop ----
    uint32_t bfr[2][4][2];
    uint32_t afr[2][2][4];

    // preload tap 0 fragments
    #pragma unroll
    for (int n8 = 0; n8 < 4; ++n8){
      uint2 bp = Bb[n8*32];
      bfr[0][n8][0] = bp.x;
      bfr[0][n8][1] = bp.y;
    }
    #pragma unroll
    for (int tt = 0; tt < 2; ++tt){
      const uint32_t* ap = Ab + tt*16;   // tap 0: ky=0, kx=0
      afr[0][tt][0] = ap[0];
      afr[0][tt][1] = ap[8];
      afr[0][tt][2] = ap[4*CIP];
      afr[0][tt][3] = ap[4*CIP + 8];
    }

    #pragma unroll
    for (int tap = 0; tap < 9; ++tap){
      int cs = tap & 1;
      int ns = cs ^ 1;
      // issue next-tap fragment loads FIRST (overlap with this tap's MMAs)
      if (tap < 8){
        int ntap = tap + 1;
        int nky = ntap / 3;
        int nkx = ntap - nky*3;
        int naoff = nky*RAW_R + nkx;
        #pragma unroll
        for (int n8 = 0; n8 < 4; ++n8){
          uint2 bp = Bb[ntap*256 + n8*32];
          bfr[ns][n8][0] = bp.x;
          bfr[ns][n8][1] = bp.y;
        }
        #pragma unroll
        for (int tt = 0; tt < 2; ++tt){
          const uint32_t* ap = Ab + naoff + tt*16;
          afr[ns][tt][0] = ap[0];
          afr[ns][tt][1] = ap[8];
          afr[ns][tt][2] = ap[4*CIP];
          afr[ns][tt][3] = ap[4*CIP + 8];
        }
      }
      // MMAs for current tap
      #pragma unroll
      for (int tt = 0; tt < 2; ++tt)
        #pragma unroll
        for (int n8 = 0; n8 < 4; ++n8)
          mma_tf32(acc[tt][n8], afr[cs][tt], bfr[cs][n8]);
    }

    asm volatile("cp.async.wait_group 0;");
    __syncthreads();
  }

  // epilogue
  int h = h0 + warpM;
  float* ob = outp + h*128 + w0;
  #pragma unroll
  for (int tt = 0; tt < 2; ++tt){
    int wbase = tt*16 + qid;
    #pragma unroll
    for (int n8 = 0; n8 < 4; ++n8){
      int co = co0 + n8*8 + rid*2;
      ob[(size_t)co*HW + wbase]          = acc[tt][n8][0];
      ob[(size_t)(co+1)*HW + wbase]      = acc[tt][n8][1];
      ob[(size_t)co*HW + wbase + 8]      = acc[tt][n8][2];
      ob[(size_t)(co+1)*HW + wbase + 8]  = acc[tt][n8][3];
    }
  }
}

// ---------------------------------------------------------------------------
// K3: broadcast add with smem plane reuse.
// ---------------------------------------------------------------------------
#define BC_PX 2048
#define BC_SMEM (8*BC_PX*4)

__global__ void __launch_bounds__(256) k_bcast2(
    const float* __restrict__ bias, float* __restrict__ out)
{
  extern __shared__ float sm[];
  int tid = threadIdx.x;
  int blk = blockIdx.x;
  int co  = blockIdx.y;
  int b   = blockIdx.z;
  int px0 = blk*BC_PX;

  #pragma unroll
  for (int s = 0; s < 4; ++s){
    const float* pu = g_ou + (((size_t)((b*4+s)*64 + co))<<14) + px0;
    const float* pv = g_ov + (((size_t)((b*4+s)*64 + co))<<14) + px0;
    #pragma unroll
    for (int rep = 0; rep < 2; ++rep){
      int j = tid*4 + rep*1024;
      *(float4*)(sm + s*BC_PX + j)     = __ldcs((const float4*)(pu + j));
      *(float4*)(sm + (4+s)*BC_PX + j) = __ldcs((const float4*)(pv + j));
    }
  }
  __syncthreads();

  float bi = __ldg(bias + co);
  #pragma unroll
  for (int sx = 0; sx < 4; ++sx){
    #pragma unroll
    for (int sy = 0; sy < 4; ++sy){
      float* op = out + (((size_t)((((b*4+sx)*4+sy)*64)+co))<<14) + px0;
      #pragma unroll
      for (int rep = 0; rep < 2; ++rep){
        int j = tid*4 + rep*1024;
        float4 a = *(float4*)(sm + sx*BC_PX + j);
        float4 c = *(float4*)(sm + (4+sy)*BC_PX + j);
        float4 o;
        o.x = a.x + c.x + bi;
        o.y = a.y + c.y + bi;
        o.z = a.z + c.z + bi;
        o.w = a.w + c.w + bi;
        __stcs((float4*)(op + j), o);
      }
    }
  }
}

// ---------------------------------------------------------------------------
extern "C" void kernel_launch(void* const* d_in, const int* in_sizes, int n_in,
                              void* d_out, int out_size)
{
  const float* u        = (const float*)d_in[0];
  const float* v        = (const float*)d_in[1];
  const float* pu_w     = (const float*)d_in[2];
  const float* pu_gamma = (const float*)d_in[3];
  const float* pu_beta  = (const float*)d_in[4];
  const float* pu_mean  = (const float*)d_in[5];
  const float* pu_var   = (const float*)d_in[6];
  const float* pv_w     = (const float*)d_in[7];
  const float* pv_gamma = (const float*)d_in[8];
  const float* pv_beta  = (const float*)d_in[9];
  const float* pv_mean  = (const float*)d_in[10];
  const float* pv_var   = (const float*)d_in[11];
  const float* conv_w   = (const float*)d_in[12];
  const float* conv_b   = (const float*)d_in[13];
  float* out = (float*)d_out;

  static int attr_set = 0;
  if (!attr_set){
    cudaFuncSetAttribute(k_pw_mma,   cudaFuncAttributeMaxDynamicSharedMemorySize, PW_SMEM);
    cudaFuncSetAttribute(k_conv_mma, cudaFuncAttributeMaxDynamicSharedMemorySize, CONV_SMEM);
    cudaFuncSetAttribute(k_bcast2,   cudaFuncAttributeMaxDynamicSharedMemorySize, BC_SMEM);
    attr_set = 1;
  }

  k_prep_w<<<288, 256>>>(conv_w);

  float* g_uf_p; cudaGetSymbolAddress((void**)&g_uf_p, g_uf);
  float* g_vf_p; cudaGetSymbolAddress((void**)&g_vf_p, g_vf);

  k_pw_mma<<<512, 256, PW_SMEM>>>(u, pu_w, pu_gamma, pu_beta, pu_mean, pu_var, g_uf_p);
  k_pw_mma<<<512, 256, PW_SMEM>>>(v, pv_w, pv_gamma, pv_beta, pv_mean, pv_var, g_vf_p);

  k_conv_mma<<<2048, 256, CONV_SMEM>>>();

  dim3 bg(8, 64, 2);
  k_bcast2<<<bg, 256, BC_SMEM>>>(conv_b, out);
}

// round 7
// speedup vs baseline: 2.8187x; 1.5805x over previous
#include <cuda_runtime.h>
#include <cuda_fp16.h>
#include <cstdint>

#define NIMG 8
#define HW 16384           // 128*128
#define IMGSZ (64*HW)

// Scratch (device globals)
__device__ __half g_ufh[NIMG*IMGSZ];   // fp16 activations, plane layout [img][ci][px]
__device__ __half g_vfh[NIMG*IMGSZ];
__device__ float  g_ou[NIMG*IMGSZ];
__device__ float  g_ov[NIMG*IMGSZ];
// fp16 conv weights, k16 B-frag layout:
// [br(2)][cgp(4)][tap(9)][co(64)][rid(4)][pp(2)] of half2 = (w[ci], w[ci+1]),
// ci = cgp*16 + 2*rid + 8*pp
__device__ uint32_t g_wPh[2*4*9*64*4*2];

__device__ __forceinline__ uint32_t to_tf32(float v){
  uint32_t r; asm("cvt.rna.tf32.f32 %0, %1;" : "=r"(r) : "f"(v)); return r;
}
__device__ __forceinline__ void mma_tf32(float* c, const uint32_t* a, const uint32_t* b){
  asm volatile(
    "mma.sync.aligned.m16n8k8.row.col.f32.tf32.tf32.f32 "
    "{%0,%1,%2,%3}, {%4,%5,%6,%7}, {%8,%9}, {%0,%1,%2,%3};"
    : "+f"(c[0]), "+f"(c[1]), "+f"(c[2]), "+f"(c[3])
    : "r"(a[0]), "r"(a[1]), "r"(a[2]), "r"(a[3]), "r"(b[0]), "r"(b[1]));
}
// fp16 k16 mma: A 4 regs, B 2 regs, C 4 f32
__device__ __forceinline__ void mma_f16(float* c, const uint32_t* a, const uint32_t* b){
  asm volatile(
    "mma.sync.aligned.m16n8k16.row.col.f32.f16.f16.f32 "
    "{%0,%1,%2,%3}, {%4,%5,%6,%7}, {%8,%9}, {%0,%1,%2,%3};"
    : "+f"(c[0]), "+f"(c[1]), "+f"(c[2]), "+f"(c[3])
    : "r"(a[0]), "r"(a[1]), "r"(a[2]), "r"(a[3]), "r"(b[0]), "r"(b[1]));
}
__device__ __forceinline__ uint32_t smem_u32(const void* p){
  uint32_t a;
  asm("{ .reg .u64 t; cvta.to.shared.u64 t, %1; cvt.u32.u64 %0, t; }" : "=r"(a) : "l"(p));
  return a;
}
__device__ __forceinline__ void cp_async16(uint32_t saddr, const void* gptr){
  asm volatile("cp.async.ca.shared.global [%0], [%1], 16;" :: "r"(saddr), "l"(gptr));
}

// ---------------------------------------------------------------------------
// K0: pack fp16 conv weights into k16 B-frag layout.
// ---------------------------------------------------------------------------
__global__ void k_prep_w(const float* __restrict__ conv_w){
  int idx = blockIdx.x*256 + threadIdx.x;    // 36864 total
  if (idx >= 36864) return;
  int pp  = idx & 1;
  int rid = (idx >> 1) & 3;
  int co  = (idx >> 3) & 63;
  int tap = (idx >> 9) % 9;
  int rest= (idx >> 9) / 9;
  int cgp = rest & 3;
  int br  = rest >> 2;
  int ci  = cgp*16 + 2*rid + 8*pp;
  float w0 = conv_w[(co*128 + br*64 + ci)*9 + tap];
  float w1 = conv_w[(co*128 + br*64 + ci + 1)*9 + tap];
  __half2 h = __floats2half2_rn(w0, w1);
  g_wPh[idx] = *(uint32_t*)&h;
}

// ---------------------------------------------------------------------------
// K1: 1x1 conv + BN + ReLU via TF32 mma. Epilogue emits fp16 plane layout.
// ---------------------------------------------------------------------------
#define PW_AP 68
#define PW_XP 264
#define PW_AW (64*PW_AP)
#define PW_XW (64*PW_XP)
#define PW_SMEM ((PW_AW + PW_XW + 128)*4)

__global__ void __launch_bounds__(256, 2) k_pw_mma(
    const float* __restrict__ x, const float* __restrict__ w,
    const float* __restrict__ gamma, const float* __restrict__ beta,
    const float* __restrict__ mean, const float* __restrict__ var,
    __half* __restrict__ out)
{
  extern __shared__ uint32_t S[];
  uint32_t* sA = S;                       // [co][PW_AP]
  uint32_t* sX = S + PW_AW;               // [ci][PW_XP]
  float* sScale = (float*)(S + PW_AW + PW_XW);
  float* sShift = sScale + 64;

  int tid  = threadIdx.x;
  int wid  = tid >> 5;
  int lane = tid & 31;
  int qid  = lane >> 2;
  int rid  = lane & 3;

  int img = blockIdx.x >> 6;
  int px0 = (blockIdx.x & 63) << 8;
  const float* xi = x + (size_t)img*IMGSZ + px0;

  for (int i = tid; i < 1024; i += 256){
    int co = i >> 4, ci4 = (i & 15) << 2;
    float4 v = *(const float4*)(w + co*64 + ci4);
    uint32_t* d = sA + co*PW_AP + ci4;
    d[0]=to_tf32(v.x); d[1]=to_tf32(v.y); d[2]=to_tf32(v.z); d[3]=to_tf32(v.w);
  }
  if (tid < 64){
    float la = gamma[tid]*rsqrtf(var[tid]+1e-5f);
    sScale[tid] = la;
    sShift[tid] = beta[tid] - mean[tid]*la;
  }
  #pragma unroll
  for (int ci_l = 0; ci_l < 8; ++ci_l){
    int ci = wid*8 + ci_l;
    const float* p = xi + ci*HW;
    uint32_t* d = sX + ci*PW_XP;
    #pragma unroll
    for (int rep = 0; rep < 2; ++rep){
      int px = lane*4 + rep*128;
      float4 v = *(const float4*)(p + px);
      d[px]=to_tf32(v.x); d[px+1]=to_tf32(v.y); d[px+2]=to_tf32(v.z); d[px+3]=to_tf32(v.w);
    }
  }
  __syncthreads();

  int pw0 = wid << 5;
  float acc[4][4][4];
  #pragma unroll
  for (int t=0;t<4;t++)
    #pragma unroll
    for (int n=0;n<4;n++)
      #pragma unroll
      for (int e=0;e<4;e++) acc[t][n][e]=0.f;

  #pragma unroll
  for (int ks = 0; ks < 8; ++ks){
    int ci0 = ks*8;
    uint32_t bfr[4][2];
    #pragma unroll
    for (int n8 = 0; n8 < 4; ++n8){
      bfr[n8][0] = sX[(ci0+rid)*PW_XP   + pw0 + n8*8 + qid];
      bfr[n8][1] = sX[(ci0+rid+4)*PW_XP + pw0 + n8*8 + qid];
    }
    #pragma unroll
    for (int t = 0; t < 4; ++t){
      uint32_t afr[4];
      const uint32_t* ap = sA + (t*16 + qid)*PW_AP + ci0 + rid;
      afr[0] = ap[0];
      afr[1] = ap[8*PW_AP];
      afr[2] = ap[4];
      afr[3] = ap[8*PW_AP + 4];
      #pragma unroll
      for (int n8 = 0; n8 < 4; ++n8)
        mma_tf32(acc[t][n8], afr, bfr[n8]);
    }
  }

  // epilogue: BN + ReLU -> fp16 plane layout (px pairs are adjacent in C frag)
  __half* ob = out + (size_t)img*IMGSZ + px0 + pw0;
  #pragma unroll
  for (int t = 0; t < 4; ++t){
    int co0t = t*16 + qid;
    float la0 = sScale[co0t],   sa0 = sShift[co0t];
    float la1 = sScale[co0t+8], sa1 = sShift[co0t+8];
    #pragma unroll
    for (int n8 = 0; n8 < 4; ++n8){
      int pc = n8*8 + rid*2;
      __half2 h0 = __floats2half2_rn(
          fmaxf(fmaf(acc[t][n8][0], la0, sa0), 0.f),
          fmaxf(fmaf(acc[t][n8][1], la0, sa0), 0.f));
      __half2 h1 = __floats2half2_rn(
          fmaxf(fmaf(acc[t][n8][2], la1, sa1), 0.f),
          fmaxf(fmaf(acc[t][n8][3], la1, sa1), 0.f));
      *(uint32_t*)(ob + (size_t)co0t*HW + pc)     = *(uint32_t*)&h0;
      *(uint32_t*)(ob + (size_t)(co0t+8)*HW + pc) = *(uint32_t*)&h1;
    }
  }
}

// ---------------------------------------------------------------------------
// K2: 3x3 conv, mma.sync FP16 m16n8k16 (half the HMMA count of tf32 k8).
// CTA: 128 px (4h x 32w) x 64 co, one image (2048 CTAs).
// Warp: 32 px (1 h-row) x 32 co; acc = 32 regs.
// Raw tile: half2 ci-pairs [pair(32)][6r x 35c pitch CIP2=232].
// Weight chunks (16 ci each) double-buffered via cp.async.
// ---------------------------------------------------------------------------
#define RAW_R 35
#define CIP2  232                    // %32==8 -> conflict-free A frags
#define SWW   4608                   // words per weight chunk [9][64][4][2]
#define RAWW  (32*CIP2)              // 7424 words
#define CONV_SMEM ((2*SWW + RAWW)*4) // 66560 B

__global__ void __launch_bounds__(256, 2) k_conv_mma()
{
  extern __shared__ uint32_t S[];
  uint32_t* swb  = S;                // two buffers of SWW
  uint32_t* Sraw = S + 2*SWW;        // [pair][CIP2]

  int tid  = threadIdx.x;
  int wid  = tid >> 5;
  int lane = tid & 31;
  int qid  = lane >> 2;
  int rid  = lane & 3;

  int bx  = blockIdx.x;
  int img = bx >> 7;               // 0..15
  int t   = bx & 127;
  int h0  = (t >> 2) << 2;
  int w0  = (t & 3)  << 5;
  int wset = img >> 3;
  const __half* in = (wset ? g_vfh : g_ufh) + (size_t)(img & 7)*IMGSZ;
  float* outp      = (wset ? g_ov  : g_ou ) + (size_t)(img & 7)*IMGSZ;

  const uint32_t* wsrc = g_wPh + (size_t)wset*18432;

  // prefetch weight chunk cgp=0 into buf0
  {
    uint32_t dst = smem_u32(swb);
    #pragma unroll
    for (int i = 0; i < 5; ++i){
      int j = tid + i*256;
      if (j < 1152) cp_async16(dst + j*16, wsrc + j*4);
    }
    asm volatile("cp.async.commit_group;");
  }

  // Stage raw tile: warp wid stages ci-pairs p = wid*4..+3.
  // Each lane loads one fp16 from the even plane and one from the odd plane,
  // packs to half2.
  #pragma unroll
  for (int pl = 0; pl < 4; ++pl){
    int p = wid*4 + pl;
    const __half* pe = in + (size_t)(2*p)*HW;
    const __half* po = in + (size_t)(2*p+1)*HW;
    uint32_t* dst = Sraw + p*CIP2;
    #pragma unroll
    for (int r = 0; r < 6; ++r){
      int gh = h0 + r - 1;
      bool vr = (unsigned)gh < 128u;
      int gw = w0 - 1 + lane;
      bool ok = vr && ((unsigned)gw < 128u);
      __half a = ok ? pe[gh*128 + gw] : __half(0.f);
      __half b = ok ? po[gh*128 + gw] : __half(0.f);
      __half2 h = __halves2half2(a, b);
      dst[r*RAW_R + lane] = *(uint32_t*)&h;
      if (lane < 2){
        int gw2 = gw + 32;
        bool ok2 = vr && ((unsigned)gw2 < 128u);
        __half a2 = ok2 ? pe[gh*128 + gw2] : __half(0.f);
        __half b2 = ok2 ? po[gh*128 + gw2] : __half(0.f);
        __half2 h2 = __halves2half2(a2, b2);
        dst[r*RAW_R + lane + 32] = *(uint32_t*)&h2;
      }
    }
  }

  asm volatile("cp.async.wait_group 0;");
  __syncthreads();

  int warpM = wid & 3;
  int co0   = (wid >> 2) << 5;

  float acc[2][4][4];
  #pragma unroll
  for (int a=0;a<2;a++)
    #pragma unroll
    for (int b=0;b<4;b++)
      #pragma unroll
      for (int e=0;e<4;e++) acc[a][b][e]=0.f;

  for (int cgp = 0; cgp < 4; ++cgp){
    int cur = cgp & 1;
    // prefetch next weight chunk into the other buffer
    if (cgp < 3){
      uint32_t dst = smem_u32(swb + (cur^1)*SWW);
      const uint32_t* src = wsrc + (cgp+1)*SWW;
      #pragma unroll
      for (int i = 0; i < 5; ++i){
        int j = tid + i*256;
        if (j < 1152) cp_async16(dst + j*16, src + j*4);
      }
      asm volatile("cp.async.commit_group;");
    }

    // A base: pair index = cgp*8 + rid (k = 2*rid..; +4 pairs for k+8)
    const uint32_t* Ab = Sraw + (cgp*8 + rid)*CIP2 + warpM*RAW_R + qid;
    // B base: [tap][co][rid][pp] pairs as uint2
    const uint2* Bb = (const uint2*)(swb + cur*SWW) + (co0 + qid)*4 + rid;

    #pragma unroll
    for (int tap = 0; tap < 9; ++tap){
      int ky = tap / 3;
      int kx = tap - ky*3;
      int aoff = ky*RAW_R + kx;

      uint32_t bfr[4][2];
      #pragma unroll
      for (int n8 = 0; n8 < 4; ++n8){
        uint2 bp = Bb[tap*256 + n8*32];
        bfr[n8][0] = bp.x;
        bfr[n8][1] = bp.y;
      }
      #pragma unroll
      for (int tt = 0; tt < 2; ++tt){
        const uint32_t* ap = Ab + aoff + tt*16;
        uint32_t afr[4];
        afr[0] = ap[0];            // px qid,    k pair rid
        afr[1] = ap[8];            // px qid+8
        afr[2] = ap[4*CIP2];       // px qid,    k pair rid+4 (k+8)
        afr[3] = ap[4*CIP2 + 8];   // px qid+8
        #pragma unroll
        for (int n8 = 0; n8 < 4; ++n8)
          mma_f16(acc[tt][n8], afr, bfr[n8]);
      }
    }

    asm volatile("cp.async.wait_group 0;");
    __syncthreads();
  }

  // epilogue (same C mapping as k8)
  int h = h0 + warpM;
  float* ob = outp + h*128 + w0;
  #pragma unroll
  for (int tt = 0; tt < 2; ++tt){
    int wbase = tt*16 + qid;
    #pragma unroll
    for (int n8 = 0; n8 < 4; ++n8){
      int co = co0 + n8*8 + rid*2;
      ob[(size_t)co*HW + wbase]          = acc[tt][n8][0];
      ob[(size_t)(co+1)*HW + wbase]      = acc[tt][n8][1];
      ob[(size_t)co*HW + wbase + 8]      = acc[tt][n8][2];
      ob[(size_t)(co+1)*HW + wbase + 8]  = acc[tt][n8][3];
    }
  }
}

// ---------------------------------------------------------------------------
// K3: broadcast add with smem plane reuse.
// ---------------------------------------------------------------------------
#define BC_PX 2048
#define BC_SMEM (8*BC_PX*4)

__global__ void __launch_bounds__(256) k_bcast2(
    const float* __restrict__ bias, float* __restrict__ out)
{
  extern __shared__ float sm[];
  int tid = threadIdx.x;
  int blk = blockIdx.x;
  int co  = blockIdx.y;
  int b   = blockIdx.z;
  int px0 = blk*BC_PX;

  #pragma unroll
  for (int s = 0; s < 4; ++s){
    const float* pu = g_ou + (((size_t)((b*4+s)*64 + co))<<14) + px0;
    const float* pv = g_ov + (((size_t)((b*4+s)*64 + co))<<14) + px0;
    #pragma unroll
    for (int rep = 0; rep < 2; ++rep){
      int j = tid*4 + rep*1024;
      *(float4*)(sm + s*BC_PX + j)     = __ldcs((const float4*)(pu + j));
      *(float4*)(sm + (4+s)*BC_PX + j) = __ldcs((const float4*)(pv + j));
    }
  }
  __syncthreads();

  float bi = __ldg(bias + co);
  #pragma unroll
  for (int sx = 0; sx < 4; ++sx){
    #pragma unroll
    for (int sy = 0; sy < 4; ++sy){
      float* op = out + (((size_t)((((b*4+sx)*4+sy)*64)+co))<<14) + px0;
      #pragma unroll
      for (int rep = 0; rep < 2; ++rep){
        int j = tid*4 + rep*1024;
        float4 a = *(float4*)(sm + sx*BC_PX + j);
        float4 c = *(float4*)(sm + (4+sy)*BC_PX + j);
        float4 o;
        o.x = a.x + c.x + bi;
        o.y = a.y + c.y + bi;
        o.z = a.z + c.z + bi;
        o.w = a.w + c.w + bi;
        __stcs((float4*)(op + j), o);
      }
    }
  }
}

// ---------------------------------------------------------------------------
extern "C" void kernel_launch(void* const* d_in, const int* in_sizes, int n_in,
                              void* d_out, int out_size)
{
  const float* u        = (const float*)d_in[0];
  const float* v        = (const float*)d_in[1];
  const float* pu_w     = (const float*)d_in[2];
  const float* pu_gamma = (const float*)d_in[3];
  const float* pu_beta  = (const float*)d_in[4];
  const float* pu_mean  = (const float*)d_in[5];
  const float* pu_var   = (const float*)d_in[6];
  const float* pv_w     = (const float*)d_in[7];
  const float* pv_gamma = (const float*)d_in[8];
  const float* pv_beta  = (const float*)d_in[9];
  const float* pv_mean  = (const float*)d_in[10];
  const float* pv_var   = (const float*)d_in[11];
  const float* conv_w   = (const float*)d_in[12];
  const float* conv_b   = (const float*)d_in[13];
  float* out = (float*)d_out;

  static int attr_set = 0;
  if (!attr_set){
    cudaFuncSetAttribute(k_pw_mma,   cudaFuncAttributeMaxDynamicSharedMemorySize, PW_SMEM);
    cudaFuncSetAttribute(k_conv_mma, cudaFuncAttributeMaxDynamicSharedMemorySize, CONV_SMEM);
    cudaFuncSetAttribute(k_bcast2,   cudaFuncAttributeMaxDynamicSharedMemorySize, BC_SMEM);
    attr_set = 1;
  }

  k_prep_w<<<144, 256>>>(conv_w);

  __half* g_ufh_p; cudaGetSymbolAddress((void**)&g_ufh_p, g_ufh);
  __half* g_vfh_p; cudaGetSymbolAddress((void**)&g_vfh_p, g_vfh);

  k_pw_mma<<<512, 256, PW_SMEM>>>(u, pu_w, pu_gamma, pu_beta, pu_mean, pu_var, g_ufh_p);
  k_pw_mma<<<512, 256, PW_SMEM>>>(v, pv_w, pv_gamma, pv_beta, pv_mean, pv_var, g_vfh_p);

  k_conv_mma<<<2048, 256, CONV_SMEM>>>();

  dim3 bg(8, 64, 2);
  k_bcast2<<<bg, 256, BC_SMEM>>>(conv_b, out);
}

// round 8
// speedup vs baseline: 2.8191x; 1.0002x over previous
#include <cuda_runtime.h>
#include <cuda_fp16.h>
#include <cstdint>

#define NIMG 8
#define HW 16384           // 128*128
#define IMGSZ (64*HW)

// Scratch (device globals)
__device__ __half g_ufh[NIMG*IMGSZ];   // fp16 activations, plane layout [img][ci][px]
__device__ __half g_vfh[NIMG*IMGSZ];
__device__ float  g_ou[NIMG*IMGSZ];
__device__ float  g_ov[NIMG*IMGSZ];
// fp16 conv weights, k16 B-frag layout:
// [br(2)][cgp(4)][tap(9)][co(64)][rid(4)][pp(2)] of half2 = (w[ci], w[ci+1]),
// ci = cgp*16 + 2*rid + 8*pp
__device__ uint32_t g_wPh[2*4*9*64*4*2];

// fp16 k16 mma: A 4 regs, B 2 regs, C 4 f32
__device__ __forceinline__ void mma_f16(float* c, const uint32_t* a, const uint32_t* b){
  asm volatile(
    "mma.sync.aligned.m16n8k16.row.col.f32.f16.f16.f32 "
    "{%0,%1,%2,%3}, {%4,%5,%6,%7}, {%8,%9}, {%0,%1,%2,%3};"
    : "+f"(c[0]), "+f"(c[1]), "+f"(c[2]), "+f"(c[3])
    : "r"(a[0]), "r"(a[1]), "r"(a[2]), "r"(a[3]), "r"(b[0]), "r"(b[1]));
}
__device__ __forceinline__ uint32_t smem_u32(const void* p){
  uint32_t a;
  asm("{ .reg .u64 t; cvta.to.shared.u64 t, %1; cvt.u32.u64 %0, t; }" : "=r"(a) : "l"(p));
  return a;
}
__device__ __forceinline__ void cp_async16(uint32_t saddr, const void* gptr){
  asm volatile("cp.async.ca.shared.global [%0], [%1], 16;" :: "r"(saddr), "l"(gptr));
}

// ---------------------------------------------------------------------------
// K0: pack fp16 conv weights into k16 B-frag layout.
// ---------------------------------------------------------------------------
__global__ void k_prep_w(const float* __restrict__ conv_w){
  int idx = blockIdx.x*256 + threadIdx.x;    // 36864 total
  if (idx >= 36864) return;
  int pp  = idx & 1;
  int rid = (idx >> 1) & 3;
  int co  = (idx >> 3) & 63;
  int tap = (idx >> 9) % 9;
  int rest= (idx >> 9) / 9;
  int cgp = rest & 3;
  int br  = rest >> 2;
  int ci  = cgp*16 + 2*rid + 8*pp;
  float w0 = conv_w[(co*128 + br*64 + ci)*9 + tap];
  float w1 = conv_w[(co*128 + br*64 + ci + 1)*9 + tap];
  __half2 h = __floats2half2_rn(w0, w1);
  g_wPh[idx] = *(uint32_t*)&h;
}

// ---------------------------------------------------------------------------
// K1: 1x1 conv + BN + ReLU via FP16 m16n8k16 mma. Emits fp16 plane layout.
// A = W[64co x 64ci] as half2 ci-pairs, B = X[ci x 256px] as half2 ci-pairs.
// ---------------------------------------------------------------------------
#define PW_PA 36                     // A pitch in half2 words (36*qid%32=4qid)
#define PW_PX 264                    // X pitch in half2 words (264%32=8)
#define PW_AW (64*PW_PA)             // 2304 words
#define PW_XW (32*PW_PX)             // 8448 words
#define PW_SMEM ((PW_AW + PW_XW + 128)*4)   // ~43.5 KB

__global__ void __launch_bounds__(256, 2) k_pw_mma(
    const float* __restrict__ x, const float* __restrict__ w,
    const float* __restrict__ gamma, const float* __restrict__ beta,
    const float* __restrict__ mean, const float* __restrict__ var,
    __half* __restrict__ out)
{
  extern __shared__ uint32_t S[];
  uint32_t* sA = S;                       // [co][PW_PA] half2 pairs
  uint32_t* sX = S + PW_AW;               // [ci_pair][PW_PX] half2 pairs
  float* sScale = (float*)(S + PW_AW + PW_XW);
  float* sShift = sScale + 64;

  int tid  = threadIdx.x;
  int wid  = tid >> 5;
  int lane = tid & 31;
  int qid  = lane >> 2;
  int rid  = lane & 3;

  int img = blockIdx.x >> 6;
  int px0 = (blockIdx.x & 63) << 8;
  const float* xi = x + (size_t)img*IMGSZ + px0;

  // stage A: 2048 half2 (co, ci-pair); thread i loads float2
  for (int i = tid; i < 2048; i += 256){
    int co = i >> 5, pr = i & 31;
    float2 v = *(const float2*)(w + co*64 + pr*2);
    __half2 h = __floats2half2_rn(v.x, v.y);
    sA[co*PW_PA + pr] = *(uint32_t*)&h;
  }
  if (tid < 64){
    float la = gamma[tid]*rsqrtf(var[tid]+1e-5f);
    sScale[tid] = la;
    sShift[tid] = beta[tid] - mean[tid]*la;
  }
  // stage X: warp wid handles ci-pairs wid*4 .. +3; 256 px each
  #pragma unroll
  for (int pl = 0; pl < 4; ++pl){
    int p = wid*4 + pl;
    const float* pe = xi + (size_t)(2*p)*HW;
    const float* po = xi + (size_t)(2*p+1)*HW;
    uint32_t* d = sX + p*PW_PX;
    #pragma unroll
    for (int rep = 0; rep < 8; ++rep){
      int px = lane + rep*32;
      __half2 h = __floats2half2_rn(pe[px], po[px]);
      d[px] = *(uint32_t*)&h;
    }
  }
  __syncthreads();

  int pw0 = wid << 5;
  float acc[4][4][4];
  #pragma unroll
  for (int t=0;t<4;t++)
    #pragma unroll
    for (int n=0;n<4;n++)
      #pragma unroll
      for (int e=0;e<4;e++) acc[t][n][e]=0.f;

  #pragma unroll
  for (int ks = 0; ks < 4; ++ks){
    int c0p = ks*8;                  // ci-pair base
    uint32_t bfr[4][2];
    #pragma unroll
    for (int n8 = 0; n8 < 4; ++n8){
      bfr[n8][0] = sX[(c0p+rid)*PW_PX   + pw0 + n8*8 + qid];
      bfr[n8][1] = sX[(c0p+4+rid)*PW_PX + pw0 + n8*8 + qid];
    }
    #pragma unroll
    for (int t = 0; t < 4; ++t){
      const uint32_t* ap = sA + (t*16 + qid)*PW_PA + c0p + rid;
      uint32_t afr[4];
      afr[0] = ap[0];
      afr[1] = ap[8*PW_PA];
      afr[2] = ap[4];
      afr[3] = ap[8*PW_PA + 4];
      #pragma unroll
      for (int n8 = 0; n8 < 4; ++n8)
        mma_f16(acc[t][n8], afr, bfr[n8]);
    }
  }

  // epilogue: BN + ReLU -> fp16 plane layout
  __half* ob = out + (size_t)img*IMGSZ + px0 + pw0;
  #pragma unroll
  for (int t = 0; t < 4; ++t){
    int co0t = t*16 + qid;
    float la0 = sScale[co0t],   sa0 = sShift[co0t];
    float la1 = sScale[co0t+8], sa1 = sShift[co0t+8];
    #pragma unroll
    for (int n8 = 0; n8 < 4; ++n8){
      int pc = n8*8 + rid*2;
      __half2 h0 = __floats2half2_rn(
          fmaxf(fmaf(acc[t][n8][0], la0, sa0), 0.f),
          fmaxf(fmaf(acc[t][n8][1], la0, sa0), 0.f));
      __half2 h1 = __floats2half2_rn(
          fmaxf(fmaf(acc[t][n8][2], la1, sa1), 0.f),
          fmaxf(fmaf(acc[t][n8][3], la1, sa1), 0.f));
      *(uint32_t*)(ob + (size_t)co0t*HW + pc)     = *(uint32_t*)&h0;
      *(uint32_t*)(ob + (size_t)(co0t+8)*HW + pc) = *(uint32_t*)&h1;
    }
  }
}

// ---------------------------------------------------------------------------
// K2: 3x3 conv, mma.sync FP16 m16n8k16 (unchanged from R7 — at legacy-path ceiling).
// ---------------------------------------------------------------------------
#define RAW_R 35
#define CIP2  232
#define SWW   4608
#define RAWW  (32*CIP2)
#define CONV_SMEM ((2*SWW + RAWW)*4)

__global__ void __launch_bounds__(256, 2) k_conv_mma()
{
  extern __shared__ uint32_t S[];
  uint32_t* swb  = S;
  uint32_t* Sraw = S + 2*SWW;

  int tid  = threadIdx.x;
  int wid  = tid >> 5;
  int lane = tid & 31;
  int qid  = lane >> 2;
  int rid  = lane & 3;

  int bx  = blockIdx.x;
  int img = bx >> 7;
  int t   = bx & 127;
  int h0  = (t >> 2) << 2;
  int w0  = (t & 3)  << 5;
  int wset = img >> 3;
  const __half* in = (wset ? g_vfh : g_ufh) + (size_t)(img & 7)*IMGSZ;
  float* outp      = (wset ? g_ov  : g_ou ) + (size_t)(img & 7)*IMGSZ;

  const uint32_t* wsrc = g_wPh + (size_t)wset*18432;

  {
    uint32_t dst = smem_u32(swb);
    #pragma unroll
    for (int i = 0; i < 5; ++i){
      int j = tid + i*256;
      if (j < 1152) cp_async16(dst + j*16, wsrc + j*4);
    }
    asm volatile("cp.async.commit_group;");
  }

  #pragma unroll
  for (int pl = 0; pl < 4; ++pl){
    int p = wid*4 + pl;
    const __half* pe = in + (size_t)(2*p)*HW;
    const __half* po = in + (size_t)(2*p+1)*HW;
    uint32_t* dst = Sraw + p*CIP2;
    #pragma unroll
    for (int r = 0; r < 6; ++r){
      int gh = h0 + r - 1;
      bool vr = (unsigned)gh < 128u;
      int gw = w0 - 1 + lane;
      bool ok = vr && ((unsigned)gw < 128u);
      __half a = ok ? pe[gh*128 + gw] : __half(0.f);
      __half b = ok ? po[gh*128 + gw] : __half(0.f);
      __half2 h = __halves2half2(a, b);
      dst[r*RAW_R + lane] = *(uint32_t*)&h;
      if (lane < 2){
        int gw2 = gw + 32;
        bool ok2 = vr && ((unsigned)gw2 < 128u);
        __half a2 = ok2 ? pe[gh*128 + gw2] : __half(0.f);
        __half b2 = ok2 ? po[gh*128 + gw2] : __half(0.f);
        __half2 h2 = __halves2half2(a2, b2);
        dst[r*RAW_R + lane + 32] = *(uint32_t*)&h2;
      }
    }
  }

  asm volatile("cp.async.wait_group 0;");
  __syncthreads();

  int warpM = wid & 3;
  int co0   = (wid >> 2) << 5;

  float acc[2][4][4];
  #pragma unroll
  for (int a=0;a<2;a++)
    #pragma unroll
    for (int b=0;b<4;b++)
      #pragma unroll
      for (int e=0;e<4;e++) acc[a][b][e]=0.f;

  for (int cgp = 0; cgp < 4; ++cgp){
    int cur = cgp & 1;
    if (cgp < 3){
      uint32_t dst = smem_u32(swb + (cur^1)*SWW);
      const uint32_t* src = wsrc + (cgp+1)*SWW;
      #pragma unroll
      for (int i = 0; i < 5; ++i){
        int j = tid + i*256;
        if (j < 1152) cp_async16(dst + j*16, src + j*4);
      }
      asm volatile("cp.async.commit_group;");
    }

    const uint32_t* Ab = Sraw + (cgp*8 + rid)*CIP2 + warpM*RAW_R + qid;
    const uint2* Bb = (const uint2*)(swb + cur*SWW) + (co0 + qid)*4 + rid;

    #pragma unroll
    for (int tap = 0; tap < 9; ++tap){
      int ky = tap / 3;
      int kx = tap - ky*3;
      int aoff = ky*RAW_R + kx;

      uint32_t bfr[4][2];
      #pragma unroll
      for (int n8 = 0; n8 < 4; ++n8){
        uint2 bp = Bb[tap*256 + n8*32];
        bfr[n8][0] = bp.x;
        bfr[n8][1] = bp.y;
      }
      #pragma unroll
      for (int tt = 0; tt < 2; ++tt){
        const uint32_t* ap = Ab + aoff + tt*16;
        uint32_t afr[4];
        afr[0] = ap[0];
        afr[1] = ap[8];
        afr[2] = ap[4*CIP2];
        afr[3] = ap[4*CIP2 + 8];
        #pragma unroll
        for (int n8 = 0; n8 < 4; ++n8)
          mma_f16(acc[tt][n8], afr, bfr[n8]);
      }
    }

    asm volatile("cp.async.wait_group 0;");
    __syncthreads();
  }

  int h = h0 + warpM;
  float* ob = outp + h*128 + w0;
  #pragma unroll
  for (int tt = 0; tt < 2; ++tt){
    int wbase = tt*16 + qid;
    #pragma unroll
    for (int n8 = 0; n8 < 4; ++n8){
      int co = co0 + n8*8 + rid*2;
      ob[(size_t)co*HW + wbase]          = acc[tt][n8][0];
      ob[(size_t)(co+1)*HW + wbase]      = acc[tt][n8][1];
      ob[(size_t)co*HW + wbase + 8]      = acc[tt][n8][2];
      ob[(size_t)(co+1)*HW + wbase + 8]  = acc[tt][n8][3];
    }
  }
}

// ---------------------------------------------------------------------------
// K3: broadcast add, register-resident (no smem, no barriers).
// Thread = (b, co, px-quad): read 4 ou + 4 ov float4 (L2-hot), write 16.
// ---------------------------------------------------------------------------
__global__ void __launch_bounds__(256) k_bcast3(
    const float* __restrict__ bias, float* __restrict__ out)
{
  int tid = threadIdx.x;
  int blk = blockIdx.x & 15;            // 16 x 1024 px
  int co  = (blockIdx.x >> 4) & 63;
  int b   = blockIdx.x >> 10;
  int px  = blk*1024 + tid*4;

  float bi = __ldg(bias + co);
  float4 uu[4], vv[4];
  #pragma unroll
  for (int s = 0; s < 4; ++s){
    uu[s] = __ldg((const float4*)(g_ou + (((size_t)((b*4+s)*64 + co))<<14) + px));
    vv[s] = __ldg((const float4*)(g_ov + (((size_t)((b*4+s)*64 + co))<<14) + px));
    uu[s].x += bi; uu[s].y += bi; uu[s].z += bi; uu[s].w += bi;
  }
  #pragma unroll
  for (int sx = 0; sx < 4; ++sx){
    #pragma unroll
    for (int sy = 0; sy < 4; ++sy){
      float4 o;
      o.x = uu[sx].x + vv[sy].x;
      o.y = uu[sx].y + vv[sy].y;
      o.z = uu[sx].z + vv[sy].z;
      o.w = uu[sx].w + vv[sy].w;
      __stcs((float4*)(out + (((size_t)((((b*4+sx)*4+sy)*64)+co))<<14) + px), o);
    }
  }
}

// ---------------------------------------------------------------------------
extern "C" void kernel_launch(void* const* d_in, const int* in_sizes, int n_in,
                              void* d_out, int out_size)
{
  const float* u        = (const float*)d_in[0];
  const float* v        = (const float*)d_in[1];
  const float* pu_w     = (const float*)d_in[2];
  const float* pu_gamma = (const float*)d_in[3];
  const float* pu_beta  = (const float*)d_in[4];
  const float* pu_mean  = (const float*)d_in[5];
  const float* pu_var   = (const float*)d_in[6];
  const float* pv_w     = (const float*)d_in[7];
  const float* pv_gamma = (const float*)d_in[8];
  const float* pv_beta  = (const float*)d_in[9];
  const float* pv_mean  = (const float*)d_in[10];
  const float* pv_var   = (const float*)d_in[11];
  const float* conv_w   = (const float*)d_in[12];
  const float* conv_b   = (const float*)d_in[13];
  float* out = (float*)d_out;

  static int attr_set = 0;
  if (!attr_set){
    cudaFuncSetAttribute(k_pw_mma,   cudaFuncAttributeMaxDynamicSharedMemorySize, PW_SMEM);
    cudaFuncSetAttribute(k_conv_mma, cudaFuncAttributeMaxDynamicSharedMemorySize, CONV_SMEM);
    attr_set = 1;
  }

  k_prep_w<<<144, 256>>>(conv_w);

  __half* g_ufh_p; cudaGetSymbolAddress((void**)&g_ufh_p, g_ufh);
  __half* g_vfh_p; cudaGetSymbolAddress((void**)&g_vfh_p, g_vfh);

  k_pw_mma<<<512, 256, PW_SMEM>>>(u, pu_w, pu_gamma, pu_beta, pu_mean, pu_var, g_ufh_p);
  k_pw_mma<<<512, 256, PW_SMEM>>>(v, pv_w, pv_gamma, pv_beta, pv_mean, pv_var, g_vfh_p);

  k_conv_mma<<<2048, 256, CONV_SMEM>>>();

  k_bcast3<<<2048, 256>>>(conv_b, out);
}

// round 9
// speedup vs baseline: 3.2855x; 1.1654x over previous
#include <cuda_runtime.h>
#include <cuda_fp16.h>
#include <cstdint>

#define NIMG 8
#define HW 16384           // 128*128
#define IMGSZ (64*HW)

// Scratch (device globals)
__device__ __half g_ufh[NIMG*IMGSZ];   // fp16 activations, plane layout [img][ci][px]
__device__ __half g_vfh[NIMG*IMGSZ];
__device__ float  g_ou[NIMG*IMGSZ];
__device__ float  g_ov[NIMG*IMGSZ];
// fp16 conv weights, k16 B-frag layout:
// [br(2)][cgp(4)][tap(9)][co(64)][rid(4)][pp(2)] of half2 = (w[ci], w[ci+1]),
// ci = cgp*16 + 2*rid + 8*pp
__device__ uint32_t g_wPh[2*4*9*64*4*2];

// fp16 k16 mma: A 4 regs, B 2 regs, C 4 f32
__device__ __forceinline__ void mma_f16(float* c, const uint32_t* a, const uint32_t* b){
  asm volatile(
    "mma.sync.aligned.m16n8k16.row.col.f32.f16.f16.f32 "
    "{%0,%1,%2,%3}, {%4,%5,%6,%7}, {%8,%9}, {%0,%1,%2,%3};"
    : "+f"(c[0]), "+f"(c[1]), "+f"(c[2]), "+f"(c[3])
    : "r"(a[0]), "r"(a[1]), "r"(a[2]), "r"(a[3]), "r"(b[0]), "r"(b[1]));
}
__device__ __forceinline__ uint32_t smem_u32(const void* p){
  uint32_t a;
  asm("{ .reg .u64 t; cvta.to.shared.u64 t, %1; cvt.u32.u64 %0, t; }" : "=r"(a) : "l"(p));
  return a;
}
__device__ __forceinline__ void cp_async16(uint32_t saddr, const void* gptr){
  asm volatile("cp.async.ca.shared.global [%0], [%1], 16;" :: "r"(saddr), "l"(gptr));
}

// ---------------------------------------------------------------------------
// K0: pack fp16 conv weights into k16 B-frag layout.
// ---------------------------------------------------------------------------
__global__ void k_prep_w(const float* __restrict__ conv_w){
  int idx = blockIdx.x*256 + threadIdx.x;    // 36864 total
  if (idx >= 36864) return;
  int pp  = idx & 1;
  int rid = (idx >> 1) & 3;
  int co  = (idx >> 3) & 63;
  int tap = (idx >> 9) % 9;
  int rest= (idx >> 9) / 9;
  int cgp = rest & 3;
  int br  = rest >> 2;
  int ci  = cgp*16 + 2*rid + 8*pp;
  float w0 = conv_w[(co*128 + br*64 + ci)*9 + tap];
  float w1 = conv_w[(co*128 + br*64 + ci + 1)*9 + tap];
  __half2 h = __floats2half2_rn(w0, w1);
  g_wPh[idx] = *(uint32_t*)&h;
}

// ---------------------------------------------------------------------------
// K1: 1x1 conv + BN + ReLU via FP16 m16n8k16 mma. Emits fp16 plane layout.
// ---------------------------------------------------------------------------
#define PW_PA 36
#define PW_PX 264
#define PW_AW (64*PW_PA)
#define PW_XW (32*PW_PX)
#define PW_SMEM ((PW_AW + PW_XW + 128)*4)

__global__ void __launch_bounds__(256, 2) k_pw_mma(
    const float* __restrict__ x, const float* __restrict__ w,
    const float* __restrict__ gamma, const float* __restrict__ beta,
    const float* __restrict__ mean, const float* __restrict__ var,
    __half* __restrict__ out)
{
  extern __shared__ uint32_t S[];
  uint32_t* sA = S;                       // [co][PW_PA] half2 pairs
  uint32_t* sX = S + PW_AW;               // [ci_pair][PW_PX] half2 pairs
  float* sScale = (float*)(S + PW_AW + PW_XW);
  float* sShift = sScale + 64;

  int tid  = threadIdx.x;
  int wid  = tid >> 5;
  int lane = tid & 31;
  int qid  = lane >> 2;
  int rid  = lane & 3;

  int img = blockIdx.x >> 6;
  int px0 = (blockIdx.x & 63) << 8;
  const float* xi = x + (size_t)img*IMGSZ + px0;

  for (int i = tid; i < 2048; i += 256){
    int co = i >> 5, pr = i & 31;
    float2 v = *(const float2*)(w + co*64 + pr*2);
    __half2 h = __floats2half2_rn(v.x, v.y);
    sA[co*PW_PA + pr] = *(uint32_t*)&h;
  }
  if (tid < 64){
    float la = gamma[tid]*rsqrtf(var[tid]+1e-5f);
    sScale[tid] = la;
    sShift[tid] = beta[tid] - mean[tid]*la;
  }
  #pragma unroll
  for (int pl = 0; pl < 4; ++pl){
    int p = wid*4 + pl;
    const float* pe = xi + (size_t)(2*p)*HW;
    const float* po = xi + (size_t)(2*p+1)*HW;
    uint32_t* d = sX + p*PW_PX;
    #pragma unroll
    for (int rep = 0; rep < 8; ++rep){
      int px = lane + rep*32;
      __half2 h = __floats2half2_rn(pe[px], po[px]);
      d[px] = *(uint32_t*)&h;
    }
  }
  __syncthreads();

  int pw0 = wid << 5;
  float acc[4][4][4];
  #pragma unroll
  for (int t=0;t<4;t++)
    #pragma unroll
    for (int n=0;n<4;n++)
      #pragma unroll
      for (int e=0;e<4;e++) acc[t][n][e]=0.f;

  #pragma unroll
  for (int ks = 0; ks < 4; ++ks){
    int c0p = ks*8;
    uint32_t bfr[4][2];
    #pragma unroll
    for (int n8 = 0; n8 < 4; ++n8){
      bfr[n8][0] = sX[(c0p+rid)*PW_PX   + pw0 + n8*8 + qid];
      bfr[n8][1] = sX[(c0p+4+rid)*PW_PX + pw0 + n8*8 + qid];
    }
    #pragma unroll
    for (int t = 0; t < 4; ++t){
      const uint32_t* ap = sA + (t*16 + qid)*PW_PA + c0p + rid;
      uint32_t afr[4];
      afr[0] = ap[0];
      afr[1] = ap[8*PW_PA];
      afr[2] = ap[4];
      afr[3] = ap[8*PW_PA + 4];
      #pragma unroll
      for (int n8 = 0; n8 < 4; ++n8)
        mma_f16(acc[t][n8], afr, bfr[n8]);
    }
  }

  __half* ob = out + (size_t)img*IMGSZ + px0 + pw0;
  #pragma unroll
  for (int t = 0; t < 4; ++t){
    int co0t = t*16 + qid;
    float la0 = sScale[co0t],   sa0 = sShift[co0t];
    float la1 = sScale[co0t+8], sa1 = sShift[co0t+8];
    #pragma unroll
    for (int n8 = 0; n8 < 4; ++n8){
      int pc = n8*8 + rid*2;
      __half2 h0 = __floats2half2_rn(
          fmaxf(fmaf(acc[t][n8][0], la0, sa0), 0.f),
          fmaxf(fmaf(acc[t][n8][1], la0, sa0), 0.f));
      __half2 h1 = __floats2half2_rn(
          fmaxf(fmaf(acc[t][n8][2], la1, sa1), 0.f),
          fmaxf(fmaf(acc[t][n8][3], la1, sa1), 0.f));
      *(uint32_t*)(ob + (size_t)co0t*HW + pc)     = *(uint32_t*)&h0;
      *(uint32_t*)(ob + (size_t)(co0t+8)*HW + pc) = *(uint32_t*)&h1;
    }
  }
}

// ---------------------------------------------------------------------------
// K2: 3x3 conv, mma.sync FP16 m16n8k16 — now 3 CTAs/SM (85-reg cap) to fix
// warp starvation (R8 evidence: tensor 20.7%, occ 24%, issue 16%).
// ---------------------------------------------------------------------------
#define RAW_R 35
#define CIP2  232
#define SWW   4608
#define RAWW  (32*CIP2)
#define CONV_SMEM ((2*SWW + RAWW)*4)

__global__ void __launch_bounds__(256, 3) k_conv_mma()
{
  extern __shared__ uint32_t S[];
  uint32_t* swb  = S;
  uint32_t* Sraw = S + 2*SWW;

  int tid  = threadIdx.x;
  int wid  = tid >> 5;
  int lane = tid & 31;
  int qid  = lane >> 2;
  int rid  = lane & 3;

  int bx  = blockIdx.x;
  int img = bx >> 7;
  int t   = bx & 127;
  int h0  = (t >> 2) << 2;
  int w0  = (t & 3)  << 5;
  int wset = img >> 3;
  const __half* in = (wset ? g_vfh : g_ufh) + (size_t)(img & 7)*IMGSZ;
  float* outp      = (wset ? g_ov  : g_ou ) + (size_t)(img & 7)*IMGSZ;

  const uint32_t* wsrc = g_wPh + (size_t)wset*18432;

  {
    uint32_t dst = smem_u32(swb);
    #pragma unroll
    for (int i = 0; i < 5; ++i){
      int j = tid + i*256;
      if (j < 1152) cp_async16(dst + j*16, wsrc + j*4);
    }
    asm volatile("cp.async.commit_group;");
  }

  #pragma unroll
  for (int pl = 0; pl < 4; ++pl){
    int p = wid*4 + pl;
    const __half* pe = in + (size_t)(2*p)*HW;
    const __half* po = in + (size_t)(2*p+1)*HW;
    uint32_t* dst = Sraw + p*CIP2;
    #pragma unroll
    for (int r = 0; r < 6; ++r){
      int gh = h0 + r - 1;
      bool vr = (unsigned)gh < 128u;
      int gw = w0 - 1 + lane;
      bool ok = vr && ((unsigned)gw < 128u);
      __half a = ok ? pe[gh*128 + gw] : __half(0.f);
      __half b = ok ? po[gh*128 + gw] : __half(0.f);
      __half2 h = __halves2half2(a, b);
      dst[r*RAW_R + lane] = *(uint32_t*)&h;
      if (lane < 2){
        int gw2 = gw + 32;
        bool ok2 = vr && ((unsigned)gw2 < 128u);
        __half a2 = ok2 ? pe[gh*128 + gw2] : __half(0.f);
        __half b2 = ok2 ? po[gh*128 + gw2] : __half(0.f);
        __half2 h2 = __halves2half2(a2, b2);
        dst[r*RAW_R + lane + 32] = *(uint32_t*)&h2;
      }
    }
  }

  asm volatile("cp.async.wait_group 0;");
  __syncthreads();

  int warpM = wid & 3;
  int co0   = (wid >> 2) << 5;

  float acc[2][4][4];
  #pragma unroll
  for (int a=0;a<2;a++)
    #pragma unroll
    for (int b=0;b<4;b++)
      #pragma unroll
      for (int e=0;e<4;e++) acc[a][b][e]=0.f;

  for (int cgp = 0; cgp < 4; ++cgp){
    int cur = cgp & 1;
    if (cgp < 3){
      uint32_t dst = smem_u32(swb + (cur^1)*SWW);
      const uint32_t* src = wsrc + (cgp+1)*SWW;
      #pragma unroll
      for (int i = 0; i < 5; ++i){
        int j = tid + i*256;
        if (j < 1152) cp_async16(dst + j*16, src + j*4);
      }
      asm volatile("cp.async.commit_group;");
    }

    const uint32_t* Ab = Sraw + (cgp*8 + rid)*CIP2 + warpM*RAW_R + qid;
    const uint2* Bb = (const uint2*)(swb + cur*SWW) + (co0 + qid)*4 + rid;

    #pragma unroll
    for (int tap = 0; tap < 9; ++tap){
      int ky = tap / 3;
      int kx = tap - ky*3;
      int aoff = ky*RAW_R + kx;

      uint32_t bfr[4][2];
      #pragma unroll
      for (int n8 = 0; n8 < 4; ++n8){
        uint2 bp = Bb[tap*256 + n8*32];
        bfr[n8][0] = bp.x;
        bfr[n8][1] = bp.y;
      }
      #pragma unroll
      for (int tt = 0; tt < 2; ++tt){
        const uint32_t* ap = Ab + aoff + tt*16;
        uint32_t afr[4];
        afr[0] = ap[0];
        afr[1] = ap[8];
        afr[2] = ap[4*CIP2];
        afr[3] = ap[4*CIP2 + 8];
        #pragma unroll
        for (int n8 = 0; n8 < 4; ++n8)
          mma_f16(acc[tt][n8], afr, bfr[n8]);
      }
    }

    asm volatile("cp.async.wait_group 0;");
    __syncthreads();
  }

  int h = h0 + warpM;
  float* ob = outp + h*128 + w0;
  #pragma unroll
  for (int tt = 0; tt < 2; ++tt){
    int wbase = tt*16 + qid;
    #pragma unroll
    for (int n8 = 0; n8 < 4; ++n8){
      int co = co0 + n8*8 + rid*2;
      ob[(size_t)co*HW + wbase]          = acc[tt][n8][0];
      ob[(size_t)(co+1)*HW + wbase]      = acc[tt][n8][1];
      ob[(size_t)co*HW + wbase + 8]      = acc[tt][n8][2];
      ob[(size_t)(co+1)*HW + wbase + 8]  = acc[tt][n8][3];
    }
  }
}

// ---------------------------------------------------------------------------
// K3: broadcast add, register-resident.
// ---------------------------------------------------------------------------
__global__ void __launch_bounds__(256) k_bcast3(
    const float* __restrict__ bias, float* __restrict__ out)
{
  int tid = threadIdx.x;
  int blk = blockIdx.x & 15;
  int co  = (blockIdx.x >> 4) & 63;
  int b   = blockIdx.x >> 10;
  int px  = blk*1024 + tid*4;

  float bi = __ldg(bias + co);
  float4 uu[4], vv[4];
  #pragma unroll
  for (int s = 0; s < 4; ++s){
    uu[s] = __ldg((const float4*)(g_ou + (((size_t)((b*4+s)*64 + co))<<14) + px));
    vv[s] = __ldg((const float4*)(g_ov + (((size_t)((b*4+s)*64 + co))<<14) + px));
    uu[s].x += bi; uu[s].y += bi; uu[s].z += bi; uu[s].w += bi;
  }
  #pragma unroll
  for (int sx = 0; sx < 4; ++sx){
    #pragma unroll
    for (int sy = 0; sy < 4; ++sy){
      float4 o;
      o.x = uu[sx].x + vv[sy].x;
      o.y = uu[sx].y + vv[sy].y;
      o.z = uu[sx].z + vv[sy].z;
      o.w = uu[sx].w + vv[sy].w;
      __stcs((float4*)(out + (((size_t)((((b*4+sx)*4+sy)*64)+co))<<14) + px), o);
    }
  }
}

// ---------------------------------------------------------------------------
extern "C" void kernel_launch(void* const* d_in, const int* in_sizes, int n_in,
                              void* d_out, int out_size)
{
  const float* u        = (const float*)d_in[0];
  const float* v        = (const float*)d_in[1];
  const float* pu_w     = (const float*)d_in[2];
  const float* pu_gamma = (const float*)d_in[3];
  const float* pu_beta  = (const float*)d_in[4];
  const float* pu_mean  = (const float*)d_in[5];
  const float* pu_var   = (const float*)d_in[6];
  const float* pv_w     = (const float*)d_in[7];
  const float* pv_gamma = (const float*)d_in[8];
  const float* pv_beta  = (const float*)d_in[9];
  const float* pv_mean  = (const float*)d_in[10];
  const float* pv_var   = (const float*)d_in[11];
  const float* conv_w   = (const float*)d_in[12];
  const float* conv_b   = (const float*)d_in[13];
  float* out = (float*)d_out;

  static int attr_set = 0;
  if (!attr_set){
    cudaFuncSetAttribute(k_pw_mma,   cudaFuncAttributeMaxDynamicSharedMemorySize, PW_SMEM);
    cudaFuncSetAttribute(k_conv_mma, cudaFuncAttributeMaxDynamicSharedMemorySize, CONV_SMEM);
    attr_set = 1;
  }

  k_prep_w<<<144, 256>>>(conv_w);

  __half* g_ufh_p; cudaGetSymbolAddress((void**)&g_ufh_p, g_ufh);
  __half* g_vfh_p; cudaGetSymbolAddress((void**)&g_vfh_p, g_vfh);

  k_pw_mma<<<512, 256, PW_SMEM>>>(u, pu_w, pu_gamma, pu_beta, pu_mean, pu_var, g_ufh_p);
  k_pw_mma<<<512, 256, PW_SMEM>>>(v, pv_w, pv_gamma, pv_beta, pv_mean, pv_var, g_vfh_p);

  k_conv_mma<<<2048, 256, CONV_SMEM>>>();

  k_bcast3<<<2048, 256>>>(conv_b, out);
}

// round 10
// speedup vs baseline: 3.6769x; 1.1191x over previous
#include <cuda_runtime.h>
#include <cuda_fp16.h>
#include <cstdint>

#define NIMG 8
#define HW 16384           // 128*128
#define IMGSZ (64*HW)

// Scratch (device globals)
__device__ __half g_ufh[NIMG*IMGSZ];   // fp16 activations, plane layout [img][ci][px]
__device__ __half g_vfh[NIMG*IMGSZ];
__device__ float  g_ou[NIMG*IMGSZ];
__device__ float  g_ov[NIMG*IMGSZ];
// fp16 conv weights, k16 B-frag layout:
// [br(2)][cgp(4)][tap(9)][co(64)][rid(4)][pp(2)] of half2 = (w[ci], w[ci+1]),
// ci = cgp*16 + 2*rid + 8*pp
__device__ uint32_t g_wPh[2*4*9*64*4*2];

// fp16 k16 mma: A 4 regs, B 2 regs, C 4 f32
__device__ __forceinline__ void mma_f16(float* c, const uint32_t* a, const uint32_t* b){
  asm volatile(
    "mma.sync.aligned.m16n8k16.row.col.f32.f16.f16.f32 "
    "{%0,%1,%2,%3}, {%4,%5,%6,%7}, {%8,%9}, {%0,%1,%2,%3};"
    : "+f"(c[0]), "+f"(c[1]), "+f"(c[2]), "+f"(c[3])
    : "r"(a[0]), "r"(a[1]), "r"(a[2]), "r"(a[3]), "r"(b[0]), "r"(b[1]));
}

// ---------------------------------------------------------------------------
// K0: pack fp16 conv weights into k16 B-frag layout.
// ---------------------------------------------------------------------------
__global__ void k_prep_w(const float* __restrict__ conv_w){
  int idx = blockIdx.x*256 + threadIdx.x;    // 36864 total
  if (idx >= 36864) return;
  int pp  = idx & 1;
  int rid = (idx >> 1) & 3;
  int co  = (idx >> 3) & 63;
  int tap = (idx >> 9) % 9;
  int rest= (idx >> 9) / 9;
  int cgp = rest & 3;
  int br  = rest >> 2;
  int ci  = cgp*16 + 2*rid + 8*pp;
  float w0 = conv_w[(co*128 + br*64 + ci)*9 + tap];
  float w1 = conv_w[(co*128 + br*64 + ci + 1)*9 + tap];
  __half2 h = __floats2half2_rn(w0, w1);
  g_wPh[idx] = *(uint32_t*)&h;
}

// ---------------------------------------------------------------------------
// K1: 1x1 conv + BN + ReLU via FP16 m16n8k16 mma. Emits fp16 plane layout.
// ---------------------------------------------------------------------------
#define PW_PA 36
#define PW_PX 264
#define PW_AW (64*PW_PA)
#define PW_XW (32*PW_PX)
#define PW_SMEM ((PW_AW + PW_XW + 128)*4)

__global__ void __launch_bounds__(256, 2) k_pw_mma(
    const float* __restrict__ x, const float* __restrict__ w,
    const float* __restrict__ gamma, const float* __restrict__ beta,
    const float* __restrict__ mean, const float* __restrict__ var,
    __half* __restrict__ out)
{
  extern __shared__ uint32_t S[];
  uint32_t* sA = S;                       // [co][PW_PA] half2 pairs
  uint32_t* sX = S + PW_AW;               // [ci_pair][PW_PX] half2 pairs
  float* sScale = (float*)(S + PW_AW + PW_XW);
  float* sShift = sScale + 64;

  int tid  = threadIdx.x;
  int wid  = tid >> 5;
  int lane = tid & 31;
  int qid  = lane >> 2;
  int rid  = lane & 3;

  int img = blockIdx.x >> 6;
  int px0 = (blockIdx.x & 63) << 8;
  const float* xi = x + (size_t)img*IMGSZ + px0;

  for (int i = tid; i < 2048; i += 256){
    int co = i >> 5, pr = i & 31;
    float2 v = *(const float2*)(w + co*64 + pr*2);
    __half2 h = __floats2half2_rn(v.x, v.y);
    sA[co*PW_PA + pr] = *(uint32_t*)&h;
  }
  if (tid < 64){
    float la = gamma[tid]*rsqrtf(var[tid]+1e-5f);
    sScale[tid] = la;
    sShift[tid] = beta[tid] - mean[tid]*la;
  }
  #pragma unroll
  for (int pl = 0; pl < 4; ++pl){
    int p = wid*4 + pl;
    const float* pe = xi + (size_t)(2*p)*HW;
    const float* po = xi + (size_t)(2*p+1)*HW;
    uint32_t* d = sX + p*PW_PX;
    #pragma unroll
    for (int rep = 0; rep < 8; ++rep){
      int px = lane + rep*32;
      __half2 h = __floats2half2_rn(pe[px], po[px]);
      d[px] = *(uint32_t*)&h;
    }
  }
  __syncthreads();

  int pw0 = wid << 5;
  float acc[4][4][4];
  #pragma unroll
  for (int t=0;t<4;t++)
    #pragma unroll
    for (int n=0;n<4;n++)
      #pragma unroll
      for (int e=0;e<4;e++) acc[t][n][e]=0.f;

  #pragma unroll
  for (int ks = 0; ks < 4; ++ks){
    int c0p = ks*8;
    uint32_t bfr[4][2];
    #pragma unroll
    for (int n8 = 0; n8 < 4; ++n8){
      bfr[n8][0] = sX[(c0p+rid)*PW_PX   + pw0 + n8*8 + qid];
      bfr[n8][1] = sX[(c0p+4+rid)*PW_PX + pw0 + n8*8 + qid];
    }
    #pragma unroll
    for (int t = 0; t < 4; ++t){
      const uint32_t* ap = sA + (t*16 + qid)*PW_PA + c0p + rid;
      uint32_t afr[4];
      afr[0] = ap[0];
      afr[1] = ap[8*PW_PA];
      afr[2] = ap[4];
      afr[3] = ap[8*PW_PA + 4];
      #pragma unroll
      for (int n8 = 0; n8 < 4; ++n8)
        mma_f16(acc[t][n8], afr, bfr[n8]);
    }
  }

  __half* ob = out + (size_t)img*IMGSZ + px0 + pw0;
  #pragma unroll
  for (int t = 0; t < 4; ++t){
    int co0t = t*16 + qid;
    float la0 = sScale[co0t],   sa0 = sShift[co0t];
    float la1 = sScale[co0t+8], sa1 = sShift[co0t+8];
    #pragma unroll
    for (int n8 = 0; n8 < 4; ++n8){
      int pc = n8*8 + rid*2;
      __half2 h0 = __floats2half2_rn(
          fmaxf(fmaf(acc[t][n8][0], la0, sa0), 0.f),
          fmaxf(fmaf(acc[t][n8][1], la0, sa0), 0.f));
      __half2 h1 = __floats2half2_rn(
          fmaxf(fmaf(acc[t][n8][2], la1, sa1), 0.f),
          fmaxf(fmaf(acc[t][n8][3], la1, sa1), 0.f));
      *(uint32_t*)(ob + (size_t)co0t*HW + pc)     = *(uint32_t*)&h0;
      *(uint32_t*)(ob + (size_t)(co0t+8)*HW + pc) = *(uint32_t*)&h1;
    }
  }
}

// ---------------------------------------------------------------------------
// K2: 3x3 conv, mma.sync FP16 m16n8k16, v5:
// - B fragments loaded straight from gmem (__ldg, L1/L2-resident 73.7KB set)
// - smem holds ONLY the raw input tile (29.7KB) -> 4 CTAs/SM, 32 warps
// - no cp.async, no barriers in the mainloop
// ---------------------------------------------------------------------------
#define RAW_R 35
#define CIP2  232
#define RAWW  (32*CIP2)
#define CONV_SMEM (RAWW*4)      // 29696 B

__global__ void __launch_bounds__(256, 4) k_conv_mma()
{
  extern __shared__ uint32_t S[];
  uint32_t* Sraw = S;           // [ci_pair(32)][CIP2]

  int tid  = threadIdx.x;
  int wid  = tid >> 5;
  int lane = tid & 31;
  int qid  = lane >> 2;
  int rid  = lane & 3;

  int bx  = blockIdx.x;
  int img = bx >> 7;
  int t   = bx & 127;
  int h0  = (t >> 2) << 2;
  int w0  = (t & 3)  << 5;
  int wset = img >> 3;
  const __half* in = (wset ? g_vfh : g_ufh) + (size_t)(img & 7)*IMGSZ;
  float* outp      = (wset ? g_ov  : g_ou ) + (size_t)(img & 7)*IMGSZ;

  // Stage raw tile: warp wid stages ci-pairs p = wid*4..+3
  #pragma unroll
  for (int pl = 0; pl < 4; ++pl){
    int p = wid*4 + pl;
    const __half* pe = in + (size_t)(2*p)*HW;
    const __half* po = in + (size_t)(2*p+1)*HW;
    uint32_t* dst = Sraw + p*CIP2;
    #pragma unroll
    for (int r = 0; r < 6; ++r){
      int gh = h0 + r - 1;
      bool vr = (unsigned)gh < 128u;
      int gw = w0 - 1 + lane;
      bool ok = vr && ((unsigned)gw < 128u);
      __half a = ok ? pe[gh*128 + gw] : __half(0.f);
      __half b = ok ? po[gh*128 + gw] : __half(0.f);
      __half2 h = __halves2half2(a, b);
      dst[r*RAW_R + lane] = *(uint32_t*)&h;
      if (lane < 2){
        int gw2 = gw + 32;
        bool ok2 = vr && ((unsigned)gw2 < 128u);
        __half a2 = ok2 ? pe[gh*128 + gw2] : __half(0.f);
        __half b2 = ok2 ? po[gh*128 + gw2] : __half(0.f);
        __half2 h2 = __halves2half2(a2, b2);
        dst[r*RAW_R + lane + 32] = *(uint32_t*)&h2;
      }
    }
  }
  __syncthreads();

  int warpM = wid & 3;
  int co0   = (wid >> 2) << 5;

  float acc[2][4][4];
  #pragma unroll
  for (int a=0;a<2;a++)
    #pragma unroll
    for (int b=0;b<4;b++)
      #pragma unroll
      for (int e=0;e<4;e++) acc[a][b][e]=0.f;

  // gmem B-frag base for this thread: uint2 index = rid + 4*co + 256*tap + 2304*cgp
  const uint2* Bb0 = (const uint2*)(g_wPh + (size_t)wset*18432) + (co0 + qid)*4 + rid;

  #pragma unroll
  for (int cgp = 0; cgp < 4; ++cgp){
    const uint32_t* Ab = Sraw + (cgp*8 + rid)*CIP2 + warpM*RAW_R + qid;
    const uint2* Bb = Bb0 + cgp*2304;

    #pragma unroll
    for (int tap = 0; tap < 9; ++tap){
      int ky = tap / 3;
      int kx = tap - ky*3;
      int aoff = ky*RAW_R + kx;

      uint32_t bfr[4][2];
      #pragma unroll
      for (int n8 = 0; n8 < 4; ++n8){
        uint2 bp = __ldg(Bb + tap*256 + n8*32);
        bfr[n8][0] = bp.x;
        bfr[n8][1] = bp.y;
      }
      #pragma unroll
      for (int tt = 0; tt < 2; ++tt){
        const uint32_t* ap = Ab + aoff + tt*16;
        uint32_t afr[4];
        afr[0] = ap[0];
        afr[1] = ap[8];
        afr[2] = ap[4*CIP2];
        afr[3] = ap[4*CIP2 + 8];
        #pragma unroll
        for (int n8 = 0; n8 < 4; ++n8)
          mma_f16(acc[tt][n8], afr, bfr[n8]);
      }
    }
  }

  // epilogue
  int h = h0 + warpM;
  float* ob = outp + h*128 + w0;
  #pragma unroll
  for (int tt = 0; tt < 2; ++tt){
    int wbase = tt*16 + qid;
    #pragma unroll
    for (int n8 = 0; n8 < 4; ++n8){
      int co = co0 + n8*8 + rid*2;
      ob[(size_t)co*HW + wbase]          = acc[tt][n8][0];
      ob[(size_t)(co+1)*HW + wbase]      = acc[tt][n8][1];
      ob[(size_t)co*HW + wbase + 8]      = acc[tt][n8][2];
      ob[(size_t)(co+1)*HW + wbase + 8]  = acc[tt][n8][3];
    }
  }
}

// ---------------------------------------------------------------------------
// K3: broadcast add, register-resident.
// ---------------------------------------------------------------------------
__global__ void __launch_bounds__(256) k_bcast3(
    const float* __restrict__ bias, float* __restrict__ out)
{
  int tid = threadIdx.x;
  int blk = blockIdx.x & 15;
  int co  = (blockIdx.x >> 4) & 63;
  int b   = blockIdx.x >> 10;
  int px  = blk*1024 + tid*4;

  float bi = __ldg(bias + co);
  float4 uu[4], vv[4];
  #pragma unroll
  for (int s = 0; s < 4; ++s){
    uu[s] = __ldg((const float4*)(g_ou + (((size_t)((b*4+s)*64 + co))<<14) + px));
    vv[s] = __ldg((const float4*)(g_ov + (((size_t)((b*4+s)*64 + co))<<14) + px));
    uu[s].x += bi; uu[s].y += bi; uu[s].z += bi; uu[s].w += bi;
  }
  #pragma unroll
  for (int sx = 0; sx < 4; ++sx){
    #pragma unroll
    for (int sy = 0; sy < 4; ++sy){
      float4 o;
      o.x = uu[sx].x + vv[sy].x;
      o.y = uu[sx].y + vv[sy].y;
      o.z = uu[sx].z + vv[sy].z;
      o.w = uu[sx].w + vv[sy].w;
      __stcs((float4*)(out + (((size_t)((((b*4+sx)*4+sy)*64)+co))<<14) + px), o);
    }
  }
}

// ---------------------------------------------------------------------------
extern "C" void kernel_launch(void* const* d_in, const int* in_sizes, int n_in,
                              void* d_out, int out_size)
{
  const float* u        = (const float*)d_in[0];
  const float* v        = (const float*)d_in[1];
  const float* pu_w     = (const float*)d_in[2];
  const float* pu_gamma = (const float*)d_in[3];
  const float* pu_beta  = (const float*)d_in[4];
  const float* pu_mean  = (const float*)d_in[5];
  const float* pu_var   = (const float*)d_in[6];
  const float* pv_w     = (const float*)d_in[7];
  const float* pv_gamma = (const float*)d_in[8];
  const float* pv_beta  = (const float*)d_in[9];
  const float* pv_mean  = (const float*)d_in[10];
  const float* pv_var   = (const float*)d_in[11];
  const float* conv_w   = (const float*)d_in[12];
  const float* conv_b   = (const float*)d_in[13];
  float* out = (float*)d_out;

  static int attr_set = 0;
  if (!attr_set){
    cudaFuncSetAttribute(k_pw_mma,   cudaFuncAttributeMaxDynamicSharedMemorySize, PW_SMEM);
    cudaFuncSetAttribute(k_conv_mma, cudaFuncAttributeMaxDynamicSharedMemorySize, CONV_SMEM);
    attr_set = 1;
  }

  k_prep_w<<<144, 256>>>(conv_w);

  __half* g_ufh_p; cudaGetSymbolAddress((void**)&g_ufh_p, g_ufh);
  __half* g_vfh_p; cudaGetSymbolAddress((void**)&g_vfh_p, g_vfh);

  k_pw_mma<<<512, 256, PW_SMEM>>>(u, pu_w, pu_gamma, pu_beta, pu_mean, pu_var, g_ufh_p);
  k_pw_mma<<<512, 256, PW_SMEM>>>(v, pv_w, pv_gamma, pv_beta, pv_mean, pv_var, g_vfh_p);

  k_conv_mma<<<2048, 256, CONV_SMEM>>>();

  k_bcast3<<<2048, 256>>>(conv_b, out);
}

// round 11
// speedup vs baseline: 4.4387x; 1.2072x over previous
#include <cuda_runtime.h>
#include <cuda_fp16.h>
#include <cstdint>

#define NIMG 8
#define HW 16384           // 128*128
#define IMGSZ (64*HW)

// Scratch (device globals)
__device__ __half g_ufh[NIMG*IMGSZ];   // fp16 activations, plane layout [img][ci][px]
__device__ __half g_vfh[NIMG*IMGSZ];
__device__ float  g_ou[NIMG*IMGSZ];
__device__ float  g_ov[NIMG*IMGSZ];
// fp16 conv weights, k16 B-frag layout:
// [br(2)][cgp(4)][tap(9)][co(64)][rid(4)][pp(2)] of half2
__device__ uint32_t g_wPh[2*4*9*64*4*2];

// fp16 k16 mma: A 4 regs, B 2 regs, C 4 f32
__device__ __forceinline__ void mma_f16(float* c, const uint32_t* a, const uint32_t* b){
  asm volatile(
    "mma.sync.aligned.m16n8k16.row.col.f32.f16.f16.f32 "
    "{%0,%1,%2,%3}, {%4,%5,%6,%7}, {%8,%9}, {%0,%1,%2,%3};"
    : "+f"(c[0]), "+f"(c[1]), "+f"(c[2]), "+f"(c[3])
    : "r"(a[0]), "r"(a[1]), "r"(a[2]), "r"(a[3]), "r"(b[0]), "r"(b[1]));
}

// ---------------------------------------------------------------------------
// K0: pack fp16 conv weights into k16 B-frag layout.
// ---------------------------------------------------------------------------
__global__ void k_prep_w(const float* __restrict__ conv_w){
  int idx = blockIdx.x*256 + threadIdx.x;    // 36864 total
  if (idx >= 36864) return;
  int pp  = idx & 1;
  int rid = (idx >> 1) & 3;
  int co  = (idx >> 3) & 63;
  int tap = (idx >> 9) % 9;
  int rest= (idx >> 9) / 9;
  int cgp = rest & 3;
  int br  = rest >> 2;
  int ci  = cgp*16 + 2*rid + 8*pp;
  float w0 = conv_w[(co*128 + br*64 + ci)*9 + tap];
  float w1 = conv_w[(co*128 + br*64 + ci + 1)*9 + tap];
  __half2 h = __floats2half2_rn(w0, w1);
  g_wPh[idx] = *(uint32_t*)&h;
}

// ---------------------------------------------------------------------------
// K1: fused (both branches) 1x1 conv + BN + ReLU via FP16 mma.
// grid (512, 2): blockIdx.y selects branch.
// ---------------------------------------------------------------------------
#define PW_PA 36
#define PW_PX 264
#define PW_AW (64*PW_PA)
#define PW_XW (32*PW_PX)
#define PW_SMEM ((PW_AW + PW_XW + 128)*4)

__global__ void __launch_bounds__(256, 2) k_pw_mma(
    const float* __restrict__ xu, const float* __restrict__ xv,
    const float* __restrict__ wu, const float* __restrict__ wv,
    const float* __restrict__ gammau, const float* __restrict__ gammav,
    const float* __restrict__ betau,  const float* __restrict__ betav,
    const float* __restrict__ meanu,  const float* __restrict__ meanv,
    const float* __restrict__ varu,   const float* __restrict__ varv)
{
  extern __shared__ uint32_t S[];
  uint32_t* sA = S;
  uint32_t* sX = S + PW_AW;
  float* sScale = (float*)(S + PW_AW + PW_XW);
  float* sShift = sScale + 64;

  int sel = blockIdx.y;
  const float* x     = sel ? xv : xu;
  const float* w     = sel ? wv : wu;
  const float* gamma = sel ? gammav : gammau;
  const float* beta  = sel ? betav  : betau;
  const float* mean  = sel ? meanv  : meanu;
  const float* var   = sel ? varv   : varu;
  __half* out = sel ? g_vfh : g_ufh;

  int tid  = threadIdx.x;
  int wid  = tid >> 5;
  int lane = tid & 31;
  int qid  = lane >> 2;
  int rid  = lane & 3;

  int img = blockIdx.x >> 6;
  int px0 = (blockIdx.x & 63) << 8;
  const float* xi = x + (size_t)img*IMGSZ + px0;

  for (int i = tid; i < 2048; i += 256){
    int co = i >> 5, pr = i & 31;
    float2 v = *(const float2*)(w + co*64 + pr*2);
    __half2 h = __floats2half2_rn(v.x, v.y);
    sA[co*PW_PA + pr] = *(uint32_t*)&h;
  }
  if (tid < 64){
    float la = gamma[tid]*rsqrtf(var[tid]+1e-5f);
    sScale[tid] = la;
    sShift[tid] = beta[tid] - mean[tid]*la;
  }
  #pragma unroll
  for (int pl = 0; pl < 4; ++pl){
    int p = wid*4 + pl;
    const float* pe = xi + (size_t)(2*p)*HW;
    const float* po = xi + (size_t)(2*p+1)*HW;
    uint32_t* d = sX + p*PW_PX;
    #pragma unroll
    for (int rep = 0; rep < 8; ++rep){
      int px = lane + rep*32;
      __half2 h = __floats2half2_rn(pe[px], po[px]);
      d[px] = *(uint32_t*)&h;
    }
  }
  __syncthreads();

  int pw0 = wid << 5;
  float acc[4][4][4];
  #pragma unroll
  for (int t=0;t<4;t++)
    #pragma unroll
    for (int n=0;n<4;n++)
      #pragma unroll
      for (int e=0;e<4;e++) acc[t][n][e]=0.f;

  #pragma unroll
  for (int ks = 0; ks < 4; ++ks){
    int c0p = ks*8;
    uint32_t bfr[4][2];
    #pragma unroll
    for (int n8 = 0; n8 < 4; ++n8){
      bfr[n8][0] = sX[(c0p+rid)*PW_PX   + pw0 + n8*8 + qid];
      bfr[n8][1] = sX[(c0p+4+rid)*PW_PX + pw0 + n8*8 + qid];
    }
    #pragma unroll
    for (int t = 0; t < 4; ++t){
      const uint32_t* ap = sA + (t*16 + qid)*PW_PA + c0p + rid;
      uint32_t afr[4];
      afr[0] = ap[0];
      afr[1] = ap[8*PW_PA];
      afr[2] = ap[4];
      afr[3] = ap[8*PW_PA + 4];
      #pragma unroll
      for (int n8 = 0; n8 < 4; ++n8)
        mma_f16(acc[t][n8], afr, bfr[n8]);
    }
  }

  __half* ob = out + (size_t)img*IMGSZ + px0 + pw0;
  #pragma unroll
  for (int t = 0; t < 4; ++t){
    int co0t = t*16 + qid;
    float la0 = sScale[co0t],   sa0 = sShift[co0t];
    float la1 = sScale[co0t+8], sa1 = sShift[co0t+8];
    #pragma unroll
    for (int n8 = 0; n8 < 4; ++n8){
      int pc = n8*8 + rid*2;
      __half2 h0 = __floats2half2_rn(
          fmaxf(fmaf(acc[t][n8][0], la0, sa0), 0.f),
          fmaxf(fmaf(acc[t][n8][1], la0, sa0), 0.f));
      __half2 h1 = __floats2half2_rn(
          fmaxf(fmaf(acc[t][n8][2], la1, sa1), 0.f),
          fmaxf(fmaf(acc[t][n8][3], la1, sa1), 0.f));
      *(uint32_t*)(ob + (size_t)co0t*HW + pc)     = *(uint32_t*)&h0;
      *(uint32_t*)(ob + (size_t)(co0t+8)*HW + pc) = *(uint32_t*)&h1;
    }
  }
}

// ---------------------------------------------------------------------------
// K2: 3x3 conv, mma.sync FP16 m16n8k16, v6:
// - A tile packed as uint2 groups: .x = ci-pair P, .y = pair P+4
//   -> per-tap A loads: 4 LDS.64 instead of 8 LDS.32
// - group stride 212 uint2 (424 words % 32 == 8) -> conflict-free LDS.64
// - B frags via __ldg (L1-resident); 27.1 KB smem -> 4 CTAs/SM
// ---------------------------------------------------------------------------
#define GSTR 212                 // uint2 per group slice (6*35 + 2 pad)
#define AROWP 35                 // uint2 per row
#define CONV_SMEM (16*GSTR*8)    // 27136 B

__global__ void __launch_bounds__(256, 4) k_conv_mma()
{
  extern __shared__ uint2 sA2[];   // [group(16)][6r][35c]

  int tid  = threadIdx.x;
  int wid  = tid >> 5;
  int lane = tid & 31;
  int qid  = lane >> 2;
  int rid  = lane & 3;

  int bx  = blockIdx.x;
  int img = bx >> 7;
  int t   = bx & 127;
  int h0  = (t >> 2) << 2;
  int w0  = (t & 3)  << 5;
  int wset = img >> 3;
  const __half* in = (wset ? g_vfh : g_ufh) + (size_t)(img & 7)*IMGSZ;
  float* outp      = (wset ? g_ov  : g_ou ) + (size_t)(img & 7)*IMGSZ;

  // Stage: warp wid handles groups g = wid*2, wid*2+1.
  // group g: cgp = g>>2, gl = g&3; pairs P1 = cgp*8+gl, P2 = P1+4.
  #pragma unroll
  for (int sub = 0; sub < 2; ++sub){
    int g  = wid*2 + sub;
    int P1 = ((g >> 2)*8) + (g & 3);
    const __half* p0 = in + (size_t)(2*P1)*HW;
    const __half* p1 = in + (size_t)(2*P1+1)*HW;
    const __half* p2 = in + (size_t)(2*P1+8)*HW;
    const __half* p3 = in + (size_t)(2*P1+9)*HW;
    uint2* dst = sA2 + g*GSTR;
    #pragma unroll
    for (int r = 0; r < 6; ++r){
      int gh = h0 + r - 1;
      bool vr = (unsigned)gh < 128u;
      int gw = w0 - 1 + lane;
      bool ok = vr && ((unsigned)gw < 128u);
      int off = gh*128 + gw;
      __half a = ok ? p0[off] : __half(0.f);
      __half b = ok ? p1[off] : __half(0.f);
      __half c = ok ? p2[off] : __half(0.f);
      __half d = ok ? p3[off] : __half(0.f);
      __half2 hx = __halves2half2(a, b);
      __half2 hy = __halves2half2(c, d);
      uint2 val; val.x = *(uint32_t*)&hx; val.y = *(uint32_t*)&hy;
      dst[r*AROWP + lane] = val;
      if (lane < 2){
        int gw2 = gw + 32;
        bool ok2 = vr && ((unsigned)gw2 < 128u);
        int off2 = gh*128 + gw2;
        __half a2 = ok2 ? p0[off2] : __half(0.f);
        __half b2 = ok2 ? p1[off2] : __half(0.f);
        __half c2 = ok2 ? p2[off2] : __half(0.f);
        __half d2 = ok2 ? p3[off2] : __half(0.f);
        __half2 hx2 = __halves2half2(a2, b2);
        __half2 hy2 = __halves2half2(c2, d2);
        uint2 v2; v2.x = *(uint32_t*)&hx2; v2.y = *(uint32_t*)&hy2;
        dst[r*AROWP + lane + 32] = v2;
      }
    }
  }
  __syncthreads();

  int warpM = wid & 3;
  int co0   = (wid >> 2) << 5;

  float acc[2][4][4];
  #pragma unroll
  for (int a=0;a<2;a++)
    #pragma unroll
    for (int b=0;b<4;b++)
      #pragma unroll
      for (int e=0;e<4;e++) acc[a][b][e]=0.f;

  const uint2* Bb0 = (const uint2*)(g_wPh + (size_t)wset*18432) + (co0 + qid)*4 + rid;

  #pragma unroll
  for (int cgp = 0; cgp < 4; ++cgp){
    const uint2* Ab = sA2 + (cgp*4 + rid)*GSTR + warpM*AROWP + qid;
    const uint2* Bb = Bb0 + cgp*2304;

    #pragma unroll
    for (int tap = 0; tap < 9; ++tap){
      int ky = tap / 3;
      int kx = tap - ky*3;
      int aoff = ky*AROWP + kx;

      uint32_t bfr[4][2];
      #pragma unroll
      for (int n8 = 0; n8 < 4; ++n8){
        uint2 bp = __ldg(Bb + tap*256 + n8*32);
        bfr[n8][0] = bp.x;
        bfr[n8][1] = bp.y;
      }
      #pragma unroll
      for (int tt = 0; tt < 2; ++tt){
        uint2 v1 = Ab[aoff + tt*16];
        uint2 v2 = Ab[aoff + tt*16 + 8];
        uint32_t afr[4];
        afr[0] = v1.x;   // (row qid,   k pair rid)
        afr[1] = v2.x;   // (row qid+8, k pair rid)
        afr[2] = v1.y;   // (row qid,   k pair rid+4)
        afr[3] = v2.y;   // (row qid+8, k pair rid+4)
        #pragma unroll
        for (int n8 = 0; n8 < 4; ++n8)
          mma_f16(acc[tt][n8], afr, bfr[n8]);
      }
    }
  }

  // epilogue
  int h = h0 + warpM;
  float* ob = outp + h*128 + w0;
  #pragma unroll
  for (int tt = 0; tt < 2; ++tt){
    int wbase = tt*16 + qid;
    #pragma unroll
    for (int n8 = 0; n8 < 4; ++n8){
      int co = co0 + n8*8 + rid*2;
      ob[(size_t)co*HW + wbase]          = acc[tt][n8][0];
      ob[(size_t)(co+1)*HW + wbase]      = acc[tt][n8][1];
      ob[(size_t)co*HW + wbase + 8]      = acc[tt][n8][2];
      ob[(size_t)(co+1)*HW + wbase + 8]  = acc[tt][n8][3];
    }
  }
}

// ---------------------------------------------------------------------------
// K3: broadcast add, register-resident.
// ---------------------------------------------------------------------------
__global__ void __launch_bounds__(256) k_bcast3(
    const float* __restrict__ bias, float* __restrict__ out)
{
  int tid = threadIdx.x;
  int blk = blockIdx.x & 15;
  int co  = (blockIdx.x >> 4) & 63;
  int b   = blockIdx.x >> 10;
  int px  = blk*1024 + tid*4;

  float bi = __ldg(bias + co);
  float4 uu[4], vv[4];
  #pragma unroll
  for (int s = 0; s < 4; ++s){
    uu[s] = __ldg((const float4*)(g_ou + (((size_t)((b*4+s)*64 + co))<<14) + px));
    vv[s] = __ldg((const float4*)(g_ov + (((size_t)((b*4+s)*64 + co))<<14) + px));
    uu[s].x += bi; uu[s].y += bi; uu[s].z += bi; uu[s].w += bi;
  }
  #pragma unroll
  for (int sx = 0; sx < 4; ++sx){
    #pragma unroll
    for (int sy = 0; sy < 4; ++sy){
      float4 o;
      o.x = uu[sx].x + vv[sy].x;
      o.y = uu[sx].y + vv[sy].y;
      o.z = uu[sx].z + vv[sy].z;
      o.w = uu[sx].w + vv[sy].w;
      __stcs((float4*)(out + (((size_t)((((b*4+sx)*4+sy)*64)+co))<<14) + px), o);
    }
  }
}

// ---------------------------------------------------------------------------
extern "C" void kernel_launch(void* const* d_in, const int* in_sizes, int n_in,
                              void* d_out, int out_size)
{
  const float* u        = (const float*)d_in[0];
  const float* v        = (const float*)d_in[1];
  const float* pu_w     = (const float*)d_in[2];
  const float* pu_gamma = (const float*)d_in[3];
  const float* pu_beta  = (const float*)d_in[4];
  const float* pu_mean  = (const float*)d_in[5];
  const float* pu_var   = (const float*)d_in[6];
  const float* pv_w     = (const float*)d_in[7];
  const float* pv_gamma = (const float*)d_in[8];
  const float* pv_beta  = (const float*)d_in[9];
  const float* pv_mean  = (const float*)d_in[10];
  const float* pv_var   = (const float*)d_in[11];
  const float* conv_w   = (const float*)d_in[12];
  const float* conv_b   = (const float*)d_in[13];
  float* out = (float*)d_out;

  static int attr_set = 0;
  if (!attr_set){
    cudaFuncSetAttribute(k_pw_mma,   cudaFuncAttributeMaxDynamicSharedMemorySize, PW_SMEM);
    cudaFuncSetAttribute(k_conv_mma, cudaFuncAttributeMaxDynamicSharedMemorySize, CONV_SMEM);
    attr_set = 1;
  }

  k_prep_w<<<144, 256>>>(conv_w);

  dim3 pwg(512, 2);
  k_pw_mma<<<pwg, 256, PW_SMEM>>>(u, v, pu_w, pv_w, pu_gamma, pv_gamma,
                                  pu_beta, pv_beta, pu_mean, pv_mean,
                                  pu_var, pv_var);

  k_conv_mma<<<2048, 256, CONV_SMEM>>>();

  k_bcast3<<<2048, 256>>>(conv_b, out);
}